// round 1
// baseline (speedup 1.0000x reference)
#include <cuda_runtime.h>
#include <cuda_bf16.h>
#include <math.h>

// Problem constants (fixed shapes for this problem instance)
#define NQ   8192        // number of queries
#define DIM  256         // model dim
#define NH   8           // heads
#define HD   32          // head dim
#define PP   25          // points per head (5x5)
#define HH   512
#define WW   512
#define HWSZ (HH * WW)   // 262144
#define DFF  1024

// ---------------------------------------------------------------------------
// Scratch (device globals; no allocation in kernel_launch)
// ---------------------------------------------------------------------------
__device__ float g_v[(size_t)HWSZ * DIM];     // value tensor (HW, 256)
__device__ float g_q[NQ * DIM];               // q = query + pos-mlp
__device__ float g_buf1[NQ * DFF];            // qp1 / ffn hidden
__device__ float g_buf2[NQ * DIM];            // qp2 / q2 / ff-out
__device__ float g_attn[NQ * NH * PP];        // attention logits -> softmax
__device__ float g_off[NQ * NH * 5];          // offsets
__device__ float g_smp[NQ * DIM];             // sampled output
__device__ float g_xq[NQ * DIM];              // post-attn LN output

// ---------------------------------------------------------------------------
// Generic tiled SGEMM:  C[M,N] = A[M,K] @ B[N,K]^T  (+ bias, epilogue)
// EPI: 0 = bias, 1 = bias+relu, 2 = bias + residual add
// GUARD=false requires K%16==0 and N%64==0 (float4 fast path)
// ---------------------------------------------------------------------------
#define BM 64
#define BN 64
#define BKT 16

template <bool GUARD, int EPI>
__global__ void sgemm_tn(const float* __restrict__ A, const float* __restrict__ B,
                         const float* __restrict__ bias, const float* __restrict__ Res,
                         float* __restrict__ C, int M, int N, int K) {
    __shared__ float As[BKT][BM];
    __shared__ float Bs[BKT][BN];
    const int tid  = threadIdx.x;
    const int brow = blockIdx.y * BM;
    const int bcol = blockIdx.x * BN;
    const int tx = tid & 15;   // column group
    const int ty = tid >> 4;   // row group
    const int lr = tid >> 2;        // 0..63 : row within tile for loads
    const int lk = (tid & 3) << 2;  // 0,4,8,12 : k offset for loads

    float acc[4][4] = {};

    for (int k0 = 0; k0 < K; k0 += BKT) {
        if (GUARD) {
            #pragma unroll
            for (int i = 0; i < 4; i++) {
                int k = k0 + lk + i;
                As[lk + i][lr] = (k < K) ? A[(size_t)(brow + lr) * K + k] : 0.f;
                int col = bcol + lr;
                Bs[lk + i][lr] = (k < K && col < N) ? B[(size_t)col * K + k] : 0.f;
            }
        } else {
            float4 av = *reinterpret_cast<const float4*>(A + (size_t)(brow + lr) * K + k0 + lk);
            As[lk + 0][lr] = av.x; As[lk + 1][lr] = av.y;
            As[lk + 2][lr] = av.z; As[lk + 3][lr] = av.w;
            float4 bv = *reinterpret_cast<const float4*>(B + (size_t)(bcol + lr) * K + k0 + lk);
            Bs[lk + 0][lr] = bv.x; Bs[lk + 1][lr] = bv.y;
            Bs[lk + 2][lr] = bv.z; Bs[lk + 3][lr] = bv.w;
        }
        __syncthreads();
        #pragma unroll
        for (int kk = 0; kk < BKT; kk++) {
            float4 a4 = *reinterpret_cast<const float4*>(&As[kk][ty << 2]);
            float4 b4 = *reinterpret_cast<const float4*>(&Bs[kk][tx << 2]);
            float ar[4] = {a4.x, a4.y, a4.z, a4.w};
            float br[4] = {b4.x, b4.y, b4.z, b4.w};
            #pragma unroll
            for (int i = 0; i < 4; i++)
                #pragma unroll
                for (int j = 0; j < 4; j++)
                    acc[i][j] = fmaf(ar[i], br[j], acc[i][j]);
        }
        __syncthreads();
    }

    #pragma unroll
    for (int i = 0; i < 4; i++) {
        int r = brow + (ty << 2) + i;
        #pragma unroll
        for (int j = 0; j < 4; j++) {
            int c = bcol + (tx << 2) + j;
            if (GUARD && c >= N) continue;
            float vv = acc[i][j] + bias[c];
            if (EPI == 1) vv = fmaxf(vv, 0.f);
            if (EPI == 2) vv += Res[(size_t)r * N + c];
            C[(size_t)r * N + c] = vv;
        }
    }
}

// ---------------------------------------------------------------------------
// Softmax over 25 logits per (query, head).  In-place on (NQ, 200).
// Block = 256 threads: warp h handles head h, lanes 0..24 hold values.
// ---------------------------------------------------------------------------
__global__ void softmax_kernel(float* __restrict__ logits) {
    int n = blockIdx.x;
    int h = threadIdx.x >> 5;
    int l = threadIdx.x & 31;
    float* ptr = logits + (size_t)n * (NH * PP) + h * PP;
    float val = (l < PP) ? ptr[l] : -1e30f;
    float m = val;
    #pragma unroll
    for (int o = 16; o; o >>= 1) m = fmaxf(m, __shfl_xor_sync(0xffffffffu, m, o));
    float e = (l < PP) ? __expf(val - m) : 0.f;
    // use precise expf to match reference closely
    if (l < PP) e = expf(val - m);
    float s = e;
    #pragma unroll
    for (int o = 16; o; o >>= 1) s += __shfl_xor_sync(0xffffffffu, s, o);
    if (l < PP) ptr[l] = e / s;
}

// ---------------------------------------------------------------------------
// Deformable bilinear sampling.
// One block (256 thr) per query; warp h = head h; lane = HD channel.
// ---------------------------------------------------------------------------
__global__ void sample_kernel(const float* __restrict__ rw,    // (NQ, 8)
                              const float* __restrict__ off,   // (NQ, 40)
                              const float* __restrict__ attn,  // (NQ, 200)
                              const float* __restrict__ v,     // (HW, 256)
                              float* __restrict__ out)         // (NQ, 256)
{
    int n    = blockIdx.x;
    int h    = threadIdx.x >> 5;
    int lane = threadIdx.x & 31;

    const float* rwn = rw + (size_t)n * 8;
    float rw0 = rwn[0], rw1 = rwn[1], rw3 = rwn[3], rw4 = rwn[4], rw6 = rwn[6];
    const float* offn = off + (size_t)n * (NH * 5) + h * 5;
    float o0 = offn[0], o1 = offn[1], o2 = offn[2], o3 = offn[3], o4 = offn[4];

    float cx = rw0 + o0 * 0.125f * rw3;
    float cy = rw1 + o1 * 0.125f * rw4;
    float sx = fmaxf(rw3 + o2 * 0.125f * rw3, 0.f);
    float sy = fmaxf(rw4 + o3 * 0.125f * rw4, 0.f);
    float ang = (rw6 + o4 * (1.0f / 16.0f)) * 6.2831853071795864769f;
    float sth, cth;
    sincosf(ang, &sth, &cth);

    const float* attnh = attn + (size_t)n * (NH * PP) + h * PP;
    const float* vh = v + h * HD + lane;

    float acc = 0.f;
    #pragma unroll
    for (int p = 0; p < PP; p++) {
        int a = p / 5, b = p % 5;
        float gx = sx * (float)(b - 2) * 0.2f;
        float gy = sy * (float)(a - 2) * 0.2f;
        float lx = cx + gx * cth - gy * sth;
        float ly = cy + gx * sth + gy * cth;
        float x = lx * (float)WW - 0.5f;
        float y = ly * (float)HH - 0.5f;
        float x0f = floorf(x), y0f = floorf(y);
        float fx = x - x0f, fy = y - y0f;
        int x0 = (int)x0f, y0 = (int)y0f;
        float ap = attnh[p];
        #pragma unroll
        for (int c = 0; c < 4; c++) {
            int dx = c & 1, dy = c >> 1;
            int xi = x0 + dx, yi = y0 + dy;
            float wx = dx ? fx : (1.f - fx);
            float wy = dy ? fy : (1.f - fy);
            bool valid = (xi >= 0) && (xi <= WW - 1) && (yi >= 0) && (yi <= HH - 1);
            if (valid) {
                float g = vh[(size_t)(yi * WW + xi) * DIM];
                acc = fmaf(ap * wx * wy, g, acc);
            }
        }
    }
    out[(size_t)n * DIM + h * HD + lane] = acc;
}

// ---------------------------------------------------------------------------
// LayerNorm over last dim (256):  out = LN(a + b) * gamma + beta
// Block = 256 threads = one row.
// ---------------------------------------------------------------------------
__global__ void ln_kernel(const float* __restrict__ A, const float* __restrict__ Bb,
                          const float* __restrict__ gamma, const float* __restrict__ beta,
                          float* __restrict__ O) {
    int n = blockIdx.x;
    int c = threadIdx.x;
    float x = A[(size_t)n * DIM + c] + Bb[(size_t)n * DIM + c];
    float s = x, sq = x * x;
    #pragma unroll
    for (int o = 16; o; o >>= 1) {
        s  += __shfl_xor_sync(0xffffffffu, s, o);
        sq += __shfl_xor_sync(0xffffffffu, sq, o);
    }
    __shared__ float sh_s[8], sh_q[8];
    if ((c & 31) == 0) { sh_s[c >> 5] = s; sh_q[c >> 5] = sq; }
    __syncthreads();
    float ts = 0.f, tq = 0.f;
    #pragma unroll
    for (int i = 0; i < 8; i++) { ts += sh_s[i]; tq += sh_q[i]; }
    float mean = ts * (1.0f / (float)DIM);
    float var  = tq * (1.0f / (float)DIM) - mean * mean;
    var = fmaxf(var, 0.f);
    float inv = rsqrtf(var + 1e-5f);
    O[(size_t)n * DIM + c] = (x - mean) * inv * gamma[c] + beta[c];
}

// ---------------------------------------------------------------------------
// Host orchestration
// ---------------------------------------------------------------------------
static inline void launch_gemm(const float* A, const float* B, const float* bias,
                               const float* Res, float* C, int M, int N, int K,
                               int epi, bool fast) {
    dim3 grid((N + BN - 1) / BN, (M + BM - 1) / BM);
    dim3 block(256);
    if (fast) {
        if (epi == 0)      sgemm_tn<false, 0><<<grid, block>>>(A, B, bias, Res, C, M, N, K);
        else if (epi == 1) sgemm_tn<false, 1><<<grid, block>>>(A, B, bias, Res, C, M, N, K);
        else               sgemm_tn<false, 2><<<grid, block>>>(A, B, bias, Res, C, M, N, K);
    } else {
        if (epi == 0)      sgemm_tn<true, 0><<<grid, block>>>(A, B, bias, Res, C, M, N, K);
        else if (epi == 1) sgemm_tn<true, 1><<<grid, block>>>(A, B, bias, Res, C, M, N, K);
        else               sgemm_tn<true, 2><<<grid, block>>>(A, B, bias, Res, C, M, N, K);
    }
}

extern "C" void kernel_launch(void* const* d_in, const int* in_sizes, int n_in,
                              void* d_out, int out_size) {
    const float* query = (const float*)d_in[0];
    const float* memory = (const float*)d_in[1];
    const float* ref_w  = (const float*)d_in[2];
    // d_in[3] memory_shape (int32), d_in[4] memory_start_idx (int64): constants here
    const float* Wp1 = (const float*)d_in[5];
    const float* bp1 = (const float*)d_in[6];
    const float* Wp2 = (const float*)d_in[7];
    const float* bp2 = (const float*)d_in[8];
    const float* Wp3 = (const float*)d_in[9];
    const float* bp3 = (const float*)d_in[10];
    const float* Wv  = (const float*)d_in[11];
    const float* bv  = (const float*)d_in[12];
    const float* Wa  = (const float*)d_in[13];
    const float* ba  = (const float*)d_in[14];
    const float* Wb  = (const float*)d_in[15];
    const float* bb  = (const float*)d_in[16];
    const float* Wo  = (const float*)d_in[17];
    const float* bo  = (const float*)d_in[18];
    const float* W1  = (const float*)d_in[19];
    const float* b1  = (const float*)d_in[20];
    const float* W2  = (const float*)d_in[21];
    const float* b2  = (const float*)d_in[22];
    const float* g2  = (const float*)d_in[23];
    const float* be2 = (const float*)d_in[24];
    const float* g3  = (const float*)d_in[25];
    const float* be3 = (const float*)d_in[26];
    float* out = (float*)d_out;

    float *v, *q, *buf1, *buf2, *attn, *off, *smp, *xq;
    cudaGetSymbolAddress((void**)&v,    g_v);
    cudaGetSymbolAddress((void**)&q,    g_q);
    cudaGetSymbolAddress((void**)&buf1, g_buf1);
    cudaGetSymbolAddress((void**)&buf2, g_buf2);
    cudaGetSymbolAddress((void**)&attn, g_attn);
    cudaGetSymbolAddress((void**)&off,  g_off);
    cudaGetSymbolAddress((void**)&smp,  g_smp);
    cudaGetSymbolAddress((void**)&xq,   g_xq);

    // 1) Positional MLP: qp = relu(rw @ Wp1^T); relu(@Wp2^T); @Wp3^T + query
    launch_gemm(ref_w, Wp1, bp1, nullptr, buf1, NQ, DIM, 8,   1, false); // K=8 guarded
    launch_gemm(buf1,  Wp2, bp2, nullptr, buf2, NQ, DIM, DIM, 1, true);
    launch_gemm(buf2,  Wp3, bp3, query,   q,    NQ, DIM, DIM, 2, true);  // q = query + qp

    // 2) Value projection (dominant GEMM)
    launch_gemm(memory, Wv, bv, nullptr, v, HWSZ, DIM, DIM, 0, true);

    // 3) Attention logits + softmax
    launch_gemm(q, Wa, ba, nullptr, attn, NQ, NH * PP, DIM, 0, false);   // N=200 guarded
    softmax_kernel<<<NQ, 256>>>(attn);

    // 4) Sampling offsets
    launch_gemm(q, Wb, bb, nullptr, off, NQ, NH * 5, DIM, 0, false);     // N=40 guarded

    // 5) Deformable bilinear sampling
    sample_kernel<<<NQ, 256>>>(ref_w, off, attn, v, smp);

    // 6) Output projection + first residual LN
    launch_gemm(smp, Wo, bo, nullptr, buf2, NQ, DIM, DIM, 0, true);      // q2
    ln_kernel<<<NQ, 256>>>(query, buf2, g2, be2, xq);                    // xq = LN(query + q2)

    // 7) FFN + final residual LN
    launch_gemm(xq,   W1, b1, nullptr, buf1, NQ, DFF, DIM, 1, true);     // hidden (relu)
    launch_gemm(buf1, W2, b2, nullptr, buf2, NQ, DIM, DFF, 0, true);     // ff out
    ln_kernel<<<NQ, 256>>>(xq, buf2, g3, be3, out);                      // out = LN(xq + ff)
}

// round 3
// speedup vs baseline: 2.8993x; 2.8993x over previous
#include <cuda_runtime.h>
#include <cuda_bf16.h>
#include <math.h>
#include <cstdint>

// Problem constants
#define NQ   8192
#define DIM  256
#define NH   8
#define HD   32
#define PP   25
#define HH   512
#define WW   512
#define HWSZ (HH * WW)
#define DFF  1024

// ---------------------------------------------------------------------------
// Scratch (device globals)
// ---------------------------------------------------------------------------
__device__ float g_v[(size_t)HWSZ * DIM];
__device__ float g_q[NQ * DIM];
__device__ float g_buf1[NQ * DFF];
__device__ float g_buf2[NQ * DIM];
__device__ float g_attn[NQ * NH * PP];
__device__ float g_off[NQ * NH * 5];
__device__ float g_smp[NQ * DIM];
__device__ float g_xq[NQ * DIM];
__device__ __nv_bfloat16 g_Wv_bf[DIM * DIM];
__device__ __nv_bfloat16 g_Wo_bf[DIM * DIM];
__device__ __nv_bfloat16 g_W1_bf[DFF * DIM];
__device__ __nv_bfloat16 g_W2_bf[DIM * DFF];

__device__ __forceinline__ uint32_t smem_to_u32(const void* p) {
    uint32_t a;
    asm("{ .reg .u64 t; cvta.to.shared.u64 t, %1; cvt.u32.u64 %0, t; }" : "=r"(a) : "l"(p));
    return a;
}

// ---------------------------------------------------------------------------
// Warp-MMA bf16 GEMM (portable HMMA path; tcgen05 unavailable at compute_103)
//   C[M,N] = A[fp32, M x K] @ B[bf16, N x K]^T  (+bias, optional relu)
// Tile: BM=128, BN=128, BK=32; 8 warps, each 64x32 (4x4 m16n8k16 tiles).
// Requires M%128==0, N%128==0, K%32==0.
// EPI: 0 = +bias, 1 = +bias+relu
// ---------------------------------------------------------------------------
#define MBM 128
#define MBN 128
#define MBK 32
#define MSTR 40   // bf16 elems per smem row (BK + 8 pad) -> 80 bytes

template <int EPI>
__global__ void __launch_bounds__(256, 2)
mma_gemm(const float* __restrict__ A, const __nv_bfloat16* __restrict__ B,
         const float* __restrict__ bias, float* __restrict__ C,
         int K, int N) {
    __shared__ __nv_bfloat16 As[MBM * MSTR];
    __shared__ __nv_bfloat16 Bs[MBN * MSTR];
    const uint32_t as_base = smem_to_u32(As);
    const uint32_t bs_base = smem_to_u32(Bs);

    const int tid  = threadIdx.x;
    const int wid  = tid >> 5;
    const int lane = tid & 31;
    const int warp_m = wid >> 2;        // 0..1
    const int warp_n = wid & 3;         // 0..3
    const int m0 = blockIdx.y * MBM;
    const int n0 = blockIdx.x * MBN;

    float acc[4][4][4];
    #pragma unroll
    for (int i = 0; i < 4; i++)
        #pragma unroll
        for (int j = 0; j < 4; j++)
            #pragma unroll
            for (int r = 0; r < 4; r++) acc[i][j][r] = 0.f;

    // ldmatrix source addresses (fixed per thread)
    const int l16 = lane & 15;
    // A: m16k16 tile: lanes 0-15 rows, lanes 16-31 col-group 1
    const uint32_t a_lm_off = (uint32_t)((warp_m * 64 + l16) * MSTR + (lane >> 4) * 8) * 2;
    // B: n8k16 tile: lanes 0-7 rows k0-7, 8-15 rows k8-15 (x2 uses lanes 0-15)
    const uint32_t b_lm_off = (uint32_t)((warp_n * 32 + (l16 & 7)) * MSTR + ((l16 >> 3) * 8)) * 2;

    for (int k0 = 0; k0 < K; k0 += MBK) {
        // ---- A tile: 128x32 fp32 -> bf16 ----
        #pragma unroll
        for (int i = 0; i < 4; i++) {
            int e = i * 256 + tid;        // float4 index
            int r = e >> 3;               // 8 float4 per row
            int c = (e & 7) << 2;         // k offset
            float4 av = *reinterpret_cast<const float4*>(A + (size_t)(m0 + r) * K + k0 + c);
            uint32_t p0, p1;
            asm("cvt.rn.satfinite.bf16x2.f32 %0, %1, %2;" : "=r"(p0) : "f"(av.y), "f"(av.x));
            asm("cvt.rn.satfinite.bf16x2.f32 %0, %1, %2;" : "=r"(p1) : "f"(av.w), "f"(av.z));
            uint32_t addr = as_base + (uint32_t)(r * MSTR + c) * 2;
            asm volatile("st.shared.v2.b32 [%0], {%1, %2};" :: "r"(addr), "r"(p0), "r"(p1));
        }
        // ---- B tile: 128x32 bf16 ----
        #pragma unroll
        for (int i = 0; i < 2; i++) {
            int e = i * 256 + tid;        // uint4 index (8 bf16)
            int r = e >> 2;               // 4 uint4 per row
            int c = (e & 3) << 3;         // k offset
            uint4 bv = *reinterpret_cast<const uint4*>(B + (size_t)(n0 + r) * K + k0 + c);
            uint32_t addr = bs_base + (uint32_t)(r * MSTR + c) * 2;
            asm volatile("st.shared.v4.b32 [%0], {%1, %2, %3, %4};"
                :: "r"(addr), "r"(bv.x), "r"(bv.y), "r"(bv.z), "r"(bv.w));
        }
        __syncthreads();

        #pragma unroll
        for (int ks = 0; ks < 2; ks++) {
            uint32_t af[4][4];
            #pragma unroll
            for (int mt = 0; mt < 4; mt++) {
                uint32_t addr = as_base + a_lm_off
                              + (uint32_t)(mt * 16 * MSTR + ks * 16) * 2;
                asm volatile("ldmatrix.sync.aligned.m8n8.x4.shared.b16 {%0,%1,%2,%3}, [%4];"
                    : "=r"(af[mt][0]), "=r"(af[mt][1]), "=r"(af[mt][2]), "=r"(af[mt][3])
                    : "r"(addr));
            }
            uint32_t bf[4][2];
            #pragma unroll
            for (int nt = 0; nt < 4; nt++) {
                uint32_t addr = bs_base + b_lm_off
                              + (uint32_t)(nt * 8 * MSTR + ks * 16) * 2;
                asm volatile("ldmatrix.sync.aligned.m8n8.x2.shared.b16 {%0,%1}, [%2];"
                    : "=r"(bf[nt][0]), "=r"(bf[nt][1]) : "r"(addr));
            }
            #pragma unroll
            for (int mt = 0; mt < 4; mt++)
                #pragma unroll
                for (int nt = 0; nt < 4; nt++) {
                    asm volatile(
                        "mma.sync.aligned.m16n8k16.row.col.f32.bf16.bf16.f32 "
                        "{%0,%1,%2,%3}, {%4,%5,%6,%7}, {%8,%9}, {%0,%1,%2,%3};"
                        : "+f"(acc[mt][nt][0]), "+f"(acc[mt][nt][1]),
                          "+f"(acc[mt][nt][2]), "+f"(acc[mt][nt][3])
                        : "r"(af[mt][0]), "r"(af[mt][1]), "r"(af[mt][2]), "r"(af[mt][3]),
                          "r"(bf[nt][0]), "r"(bf[nt][1]));
                }
        }
        __syncthreads();
    }

    // ---- epilogue ----
    const int row_in = lane >> 2;
    const int col_in = (lane & 3) << 1;
    #pragma unroll
    for (int mt = 0; mt < 4; mt++) {
        #pragma unroll
        for (int nt = 0; nt < 4; nt++) {
            int n = n0 + warp_n * 32 + nt * 8 + col_in;
            float b0 = bias[n], b1 = bias[n + 1];
            #pragma unroll
            for (int half = 0; half < 2; half++) {
                int m = m0 + warp_m * 64 + mt * 16 + row_in + half * 8;
                float2 o;
                o.x = acc[mt][nt][half * 2 + 0] + b0;
                o.y = acc[mt][nt][half * 2 + 1] + b1;
                if (EPI == 1) { o.x = fmaxf(o.x, 0.f); o.y = fmaxf(o.y, 0.f); }
                *reinterpret_cast<float2*>(C + (size_t)m * N + n) = o;
            }
        }
    }
}

// ---------------------------------------------------------------------------
// fp32->bf16 conversion
// ---------------------------------------------------------------------------
__global__ void f2bf_kernel(const float* __restrict__ src, __nv_bfloat16* __restrict__ dst, int n) {
    int i = blockIdx.x * 256 + threadIdx.x;
    if (i < n) dst[i] = __float2bfloat16(src[i]);
}

// ---------------------------------------------------------------------------
// fp32 SGEMM (accuracy-sensitive small GEMMs)
// ---------------------------------------------------------------------------
#define BM 64
#define BN 64
#define BKT 16

template <bool GUARD, int EPI>
__global__ void sgemm_tn(const float* __restrict__ A, const float* __restrict__ B,
                         const float* __restrict__ bias, const float* __restrict__ Res,
                         float* __restrict__ C, int M, int N, int K) {
    __shared__ float As[BKT][BM];
    __shared__ float Bs[BKT][BN];
    const int tid  = threadIdx.x;
    const int brow = blockIdx.y * BM;
    const int bcol = blockIdx.x * BN;
    const int tx = tid & 15;
    const int ty = tid >> 4;
    const int lr = tid >> 2;
    const int lk = (tid & 3) << 2;

    float acc[4][4] = {};
    for (int k0 = 0; k0 < K; k0 += BKT) {
        if (GUARD) {
            #pragma unroll
            for (int i = 0; i < 4; i++) {
                int k = k0 + lk + i;
                As[lk + i][lr] = (k < K) ? A[(size_t)(brow + lr) * K + k] : 0.f;
                int col = bcol + lr;
                Bs[lk + i][lr] = (k < K && col < N) ? B[(size_t)col * K + k] : 0.f;
            }
        } else {
            float4 av = *reinterpret_cast<const float4*>(A + (size_t)(brow + lr) * K + k0 + lk);
            As[lk + 0][lr] = av.x; As[lk + 1][lr] = av.y;
            As[lk + 2][lr] = av.z; As[lk + 3][lr] = av.w;
            float4 bv = *reinterpret_cast<const float4*>(B + (size_t)(bcol + lr) * K + k0 + lk);
            Bs[lk + 0][lr] = bv.x; Bs[lk + 1][lr] = bv.y;
            Bs[lk + 2][lr] = bv.z; Bs[lk + 3][lr] = bv.w;
        }
        __syncthreads();
        #pragma unroll
        for (int kk = 0; kk < BKT; kk++) {
            float4 a4 = *reinterpret_cast<const float4*>(&As[kk][ty << 2]);
            float4 b4 = *reinterpret_cast<const float4*>(&Bs[kk][tx << 2]);
            float ar[4] = {a4.x, a4.y, a4.z, a4.w};
            float br[4] = {b4.x, b4.y, b4.z, b4.w};
            #pragma unroll
            for (int i = 0; i < 4; i++)
                #pragma unroll
                for (int j = 0; j < 4; j++)
                    acc[i][j] = fmaf(ar[i], br[j], acc[i][j]);
        }
        __syncthreads();
    }
    #pragma unroll
    for (int i = 0; i < 4; i++) {
        int r = brow + (ty << 2) + i;
        #pragma unroll
        for (int j = 0; j < 4; j++) {
            int c = bcol + (tx << 2) + j;
            if (GUARD && c >= N) continue;
            float vv = acc[i][j] + bias[c];
            if (EPI == 1) vv = fmaxf(vv, 0.f);
            if (EPI == 2) vv += Res[(size_t)r * N + c];
            C[(size_t)r * N + c] = vv;
        }
    }
}

// ---------------------------------------------------------------------------
// Softmax over 25 logits per (query, head)
// ---------------------------------------------------------------------------
__global__ void softmax_kernel(float* __restrict__ logits) {
    int n = blockIdx.x;
    int h = threadIdx.x >> 5;
    int l = threadIdx.x & 31;
    float* ptr = logits + (size_t)n * (NH * PP) + h * PP;
    float val = (l < PP) ? ptr[l] : -1e30f;
    float m = val;
    #pragma unroll
    for (int o = 16; o; o >>= 1) m = fmaxf(m, __shfl_xor_sync(0xffffffffu, m, o));
    float e = (l < PP) ? expf(val - m) : 0.f;
    float s = e;
    #pragma unroll
    for (int o = 16; o; o >>= 1) s += __shfl_xor_sync(0xffffffffu, s, o);
    if (l < PP) ptr[l] = e / s;
}

// ---------------------------------------------------------------------------
// Deformable bilinear sampling
// ---------------------------------------------------------------------------
__global__ void sample_kernel(const float* __restrict__ rw,
                              const float* __restrict__ off,
                              const float* __restrict__ attn,
                              const float* __restrict__ v,
                              float* __restrict__ out) {
    int n    = blockIdx.x;
    int h    = threadIdx.x >> 5;
    int lane = threadIdx.x & 31;

    const float* rwn = rw + (size_t)n * 8;
    float rw0 = rwn[0], rw1 = rwn[1], rw3 = rwn[3], rw4 = rwn[4], rw6 = rwn[6];
    const float* offn = off + (size_t)n * (NH * 5) + h * 5;
    float o0 = offn[0], o1 = offn[1], o2 = offn[2], o3 = offn[3], o4 = offn[4];

    float cx = rw0 + o0 * 0.125f * rw3;
    float cy = rw1 + o1 * 0.125f * rw4;
    float sx = fmaxf(rw3 + o2 * 0.125f * rw3, 0.f);
    float sy = fmaxf(rw4 + o3 * 0.125f * rw4, 0.f);
    float ang = (rw6 + o4 * (1.0f / 16.0f)) * 6.2831853071795864769f;
    float sth, cth;
    sincosf(ang, &sth, &cth);

    const float* attnh = attn + (size_t)n * (NH * PP) + h * PP;
    const float* vh = v + h * HD + lane;

    float acc = 0.f;
    #pragma unroll
    for (int p = 0; p < PP; p++) {
        int a = p / 5, b = p % 5;
        float gx = sx * (float)(b - 2) * 0.2f;
        float gy = sy * (float)(a - 2) * 0.2f;
        float lx = cx + gx * cth - gy * sth;
        float ly = cy + gx * sth + gy * cth;
        float x = lx * (float)WW - 0.5f;
        float y = ly * (float)HH - 0.5f;
        float x0f = floorf(x), y0f = floorf(y);
        float fx = x - x0f, fy = y - y0f;
        int x0 = (int)x0f, y0 = (int)y0f;
        float ap = attnh[p];
        #pragma unroll
        for (int c = 0; c < 4; c++) {
            int dx = c & 1, dy = c >> 1;
            int xi = x0 + dx, yi = y0 + dy;
            float wx = dx ? fx : (1.f - fx);
            float wy = dy ? fy : (1.f - fy);
            bool valid = (xi >= 0) && (xi <= WW - 1) && (yi >= 0) && (yi <= HH - 1);
            if (valid) {
                float g = vh[(size_t)(yi * WW + xi) * DIM];
                acc = fmaf(ap * wx * wy, g, acc);
            }
        }
    }
    out[(size_t)n * DIM + h * HD + lane] = acc;
}

// ---------------------------------------------------------------------------
// LayerNorm (residual add + LN)
// ---------------------------------------------------------------------------
__global__ void ln_kernel(const float* __restrict__ A, const float* __restrict__ Bb,
                          const float* __restrict__ gamma, const float* __restrict__ beta,
                          float* __restrict__ O) {
    int n = blockIdx.x;
    int c = threadIdx.x;
    float x = A[(size_t)n * DIM + c] + Bb[(size_t)n * DIM + c];
    float s = x, sq = x * x;
    #pragma unroll
    for (int o = 16; o; o >>= 1) {
        s  += __shfl_xor_sync(0xffffffffu, s, o);
        sq += __shfl_xor_sync(0xffffffffu, sq, o);
    }
    __shared__ float sh_s[8], sh_q[8];
    if ((c & 31) == 0) { sh_s[c >> 5] = s; sh_q[c >> 5] = sq; }
    __syncthreads();
    float ts = 0.f, tq = 0.f;
    #pragma unroll
    for (int i = 0; i < 8; i++) { ts += sh_s[i]; tq += sh_q[i]; }
    float mean = ts * (1.0f / (float)DIM);
    float var  = tq * (1.0f / (float)DIM) - mean * mean;
    var = fmaxf(var, 0.f);
    float inv = rsqrtf(var + 1e-5f);
    O[(size_t)n * DIM + c] = (x - mean) * inv * gamma[c] + beta[c];
}

// ---------------------------------------------------------------------------
// Host orchestration
// ---------------------------------------------------------------------------
static inline void launch_sgemm(const float* A, const float* B, const float* bias,
                                const float* Res, float* C, int M, int N, int K,
                                int epi, bool fast) {
    dim3 grid((N + BN - 1) / BN, (M + BM - 1) / BM);
    dim3 block(256);
    if (fast) {
        if (epi == 0)      sgemm_tn<false, 0><<<grid, block>>>(A, B, bias, Res, C, M, N, K);
        else if (epi == 1) sgemm_tn<false, 1><<<grid, block>>>(A, B, bias, Res, C, M, N, K);
        else               sgemm_tn<false, 2><<<grid, block>>>(A, B, bias, Res, C, M, N, K);
    } else {
        if (epi == 0)      sgemm_tn<true, 0><<<grid, block>>>(A, B, bias, Res, C, M, N, K);
        else if (epi == 1) sgemm_tn<true, 1><<<grid, block>>>(A, B, bias, Res, C, M, N, K);
        else               sgemm_tn<true, 2><<<grid, block>>>(A, B, bias, Res, C, M, N, K);
    }
}

extern "C" void kernel_launch(void* const* d_in, const int* in_sizes, int n_in,
                              void* d_out, int out_size) {
    const float* query = (const float*)d_in[0];
    const float* memory = (const float*)d_in[1];
    const float* ref_w  = (const float*)d_in[2];
    const float* Wp1 = (const float*)d_in[5];
    const float* bp1 = (const float*)d_in[6];
    const float* Wp2 = (const float*)d_in[7];
    const float* bp2 = (const float*)d_in[8];
    const float* Wp3 = (const float*)d_in[9];
    const float* bp3 = (const float*)d_in[10];
    const float* Wv  = (const float*)d_in[11];
    const float* bv  = (const float*)d_in[12];
    const float* Wa  = (const float*)d_in[13];
    const float* ba  = (const float*)d_in[14];
    const float* Wb  = (const float*)d_in[15];
    const float* bb  = (const float*)d_in[16];
    const float* Wo  = (const float*)d_in[17];
    const float* bo  = (const float*)d_in[18];
    const float* W1  = (const float*)d_in[19];
    const float* b1  = (const float*)d_in[20];
    const float* W2  = (const float*)d_in[21];
    const float* b2  = (const float*)d_in[22];
    const float* g2  = (const float*)d_in[23];
    const float* be2 = (const float*)d_in[24];
    const float* g3  = (const float*)d_in[25];
    const float* be3 = (const float*)d_in[26];
    float* out = (float*)d_out;

    float *v, *q, *buf1, *buf2, *attn, *off, *smp, *xq;
    __nv_bfloat16 *Wv_bf, *Wo_bf, *W1_bf, *W2_bf;
    cudaGetSymbolAddress((void**)&v,    g_v);
    cudaGetSymbolAddress((void**)&q,    g_q);
    cudaGetSymbolAddress((void**)&buf1, g_buf1);
    cudaGetSymbolAddress((void**)&buf2, g_buf2);
    cudaGetSymbolAddress((void**)&attn, g_attn);
    cudaGetSymbolAddress((void**)&off,  g_off);
    cudaGetSymbolAddress((void**)&smp,  g_smp);
    cudaGetSymbolAddress((void**)&xq,   g_xq);
    cudaGetSymbolAddress((void**)&Wv_bf, g_Wv_bf);
    cudaGetSymbolAddress((void**)&Wo_bf, g_Wo_bf);
    cudaGetSymbolAddress((void**)&W1_bf, g_W1_bf);
    cudaGetSymbolAddress((void**)&W2_bf, g_W2_bf);

    // 0) Weight conversions to bf16
    f2bf_kernel<<<(DIM * DIM + 255) / 256, 256>>>(Wv, Wv_bf, DIM * DIM);
    f2bf_kernel<<<(DIM * DIM + 255) / 256, 256>>>(Wo, Wo_bf, DIM * DIM);
    f2bf_kernel<<<(DFF * DIM + 255) / 256, 256>>>(W1, W1_bf, DFF * DIM);
    f2bf_kernel<<<(DIM * DFF + 255) / 256, 256>>>(W2, W2_bf, DIM * DFF);

    // 1) Positional MLP (fp32 for location accuracy)
    launch_sgemm(ref_w, Wp1, bp1, nullptr, buf1, NQ, DIM, 8,   1, false);
    launch_sgemm(buf1,  Wp2, bp2, nullptr, buf2, NQ, DIM, DIM, 1, true);
    launch_sgemm(buf2,  Wp3, bp3, query,   q,    NQ, DIM, DIM, 2, true);

    // 2) Value projection (bf16 tensor cores)
    mma_gemm<0><<<dim3(DIM / MBN, HWSZ / MBM), 256>>>(memory, Wv_bf, bv, v, DIM, DIM);

    // 3) Attention logits + softmax (fp32)
    launch_sgemm(q, Wa, ba, nullptr, attn, NQ, NH * PP, DIM, 0, false);
    softmax_kernel<<<NQ, 256>>>(attn);

    // 4) Sampling offsets (fp32)
    launch_sgemm(q, Wb, bb, nullptr, off, NQ, NH * 5, DIM, 0, false);

    // 5) Deformable bilinear sampling
    sample_kernel<<<NQ, 256>>>(ref_w, off, attn, v, smp);

    // 6) Output projection (bf16) + residual LN
    mma_gemm<0><<<dim3(DIM / MBN, NQ / MBM), 256>>>(smp, Wo_bf, bo, buf2, DIM, DIM);
    ln_kernel<<<NQ, 256>>>(query, buf2, g2, be2, xq);

    // 7) FFN (bf16) + final LN
    mma_gemm<1><<<dim3(DFF / MBN, NQ / MBM), 256>>>(xq, W1_bf, b1, buf1, DIM, DFF);
    mma_gemm<0><<<dim3(DIM / MBN, NQ / MBM), 256>>>(buf1, W2_bf, b2, buf2, DFF, DIM);
    ln_kernel<<<NQ, 256>>>(xq, buf2, g3, be3, out);
}

// round 5
// speedup vs baseline: 3.9210x; 1.3524x over previous
#include <cuda_runtime.h>
#include <cuda_bf16.h>
#include <math.h>
#include <cstdint>

// Problem constants
#define NQ   8192
#define DIM  256
#define NH   8
#define HD   32
#define PP   25
#define HH   512
#define WW   512
#define HWSZ (HH * WW)
#define DFF  1024

// ---------------------------------------------------------------------------
// Scratch (device globals)
// ---------------------------------------------------------------------------
__device__ __nv_bfloat16 g_v_bf[(size_t)HWSZ * DIM];   // value tensor bf16
__device__ float g_q[NQ * DIM];
__device__ float g_buf1[NQ * DFF];                     // pos1 out / ao / ffn hidden
__device__ float g_buf2[NQ * DIM];
__device__ float g_smp[NQ * DIM];
__device__ float g_xq[NQ * DIM];
__device__ __nv_bfloat16 g_Wv_bf[DIM * DIM];
__device__ __nv_bfloat16 g_Wo_bf[DIM * DIM];
__device__ __nv_bfloat16 g_W1_bf[DFF * DIM];
__device__ __nv_bfloat16 g_W2_bf[DIM * DFF];
__device__ __nv_bfloat16 g_Wp2_bf[DIM * DIM];
__device__ __nv_bfloat16 g_Wp3_bf[DIM * DIM];
__device__ __nv_bfloat16 g_Wab_hi[DIM * DIM];          // [Wa(200); Wb(40); 0(16)] hi
__device__ __nv_bfloat16 g_Wab_lo[DIM * DIM];          // lo residual
__device__ float g_bab[DIM];

__device__ __forceinline__ uint32_t smem_to_u32(const void* p) {
    uint32_t a;
    asm("{ .reg .u64 t; cvta.to.shared.u64 t, %1; cvt.u32.u64 %0, t; }" : "=r"(a) : "l"(p));
    return a;
}

#define MBM 128
#define MBN 128
#define MBK 32
#define MSTR 40   // smem row stride: 20 words, 20 % 8 == 4 -> conflict-free ldmatrix

// ---------------------------------------------------------------------------
// Generic warp-MMA bf16 GEMM:  C[M,N] = A[fp32,MxK] @ B[bf16,NxK]^T
// EPI: 0=+bias, 1=+bias+relu, 2=+bias+Res
// ---------------------------------------------------------------------------
template <int EPI>
__global__ void __launch_bounds__(256, 2)
mma_gemm(const float* __restrict__ A, const __nv_bfloat16* __restrict__ B,
         const float* __restrict__ bias, const float* __restrict__ Res,
         float* __restrict__ C, int K, int N) {
    __shared__ __nv_bfloat16 As[MBM * MSTR];
    __shared__ __nv_bfloat16 Bs[MBN * MSTR];
    const uint32_t as_base = smem_to_u32(As);
    const uint32_t bs_base = smem_to_u32(Bs);

    const int tid  = threadIdx.x;
    const int wid  = tid >> 5;
    const int lane = tid & 31;
    const int warp_m = wid >> 2;
    const int warp_n = wid & 3;
    const int m0 = blockIdx.y * MBM;
    const int n0 = blockIdx.x * MBN;

    float acc[4][4][4];
    #pragma unroll
    for (int i = 0; i < 4; i++)
        #pragma unroll
        for (int j = 0; j < 4; j++)
            #pragma unroll
            for (int r = 0; r < 4; r++) acc[i][j][r] = 0.f;

    const int l16 = lane & 15;
    const uint32_t a_lm_off = (uint32_t)((warp_m * 64 + l16) * MSTR + (lane >> 4) * 8) * 2;
    const uint32_t b_lm_off = (uint32_t)((warp_n * 32 + (l16 & 7)) * MSTR + ((l16 >> 3) * 8)) * 2;

    for (int k0 = 0; k0 < K; k0 += MBK) {
        #pragma unroll
        for (int i = 0; i < 4; i++) {
            int e = i * 256 + tid;
            int r = e >> 3;
            int c = (e & 7) << 2;
            float4 av = *reinterpret_cast<const float4*>(A + (size_t)(m0 + r) * K + k0 + c);
            uint32_t p0, p1;
            asm("cvt.rn.satfinite.bf16x2.f32 %0, %1, %2;" : "=r"(p0) : "f"(av.y), "f"(av.x));
            asm("cvt.rn.satfinite.bf16x2.f32 %0, %1, %2;" : "=r"(p1) : "f"(av.w), "f"(av.z));
            uint32_t addr = as_base + (uint32_t)(r * MSTR + c) * 2;
            asm volatile("st.shared.v2.b32 [%0], {%1, %2};" :: "r"(addr), "r"(p0), "r"(p1));
        }
        #pragma unroll
        for (int i = 0; i < 2; i++) {
            int e = i * 256 + tid;
            int r = e >> 2;
            int c = (e & 3) << 3;
            uint4 bv = *reinterpret_cast<const uint4*>(B + (size_t)(n0 + r) * K + k0 + c);
            uint32_t addr = bs_base + (uint32_t)(r * MSTR + c) * 2;
            asm volatile("st.shared.v4.b32 [%0], {%1, %2, %3, %4};"
                :: "r"(addr), "r"(bv.x), "r"(bv.y), "r"(bv.z), "r"(bv.w));
        }
        __syncthreads();

        #pragma unroll
        for (int ks = 0; ks < 2; ks++) {
            uint32_t af[4][4];
            #pragma unroll
            for (int mt = 0; mt < 4; mt++) {
                uint32_t addr = as_base + a_lm_off + (uint32_t)(mt * 16 * MSTR + ks * 16) * 2;
                asm volatile("ldmatrix.sync.aligned.m8n8.x4.shared.b16 {%0,%1,%2,%3}, [%4];"
                    : "=r"(af[mt][0]), "=r"(af[mt][1]), "=r"(af[mt][2]), "=r"(af[mt][3])
                    : "r"(addr));
            }
            uint32_t bf[4][2];
            #pragma unroll
            for (int nt = 0; nt < 4; nt++) {
                uint32_t addr = bs_base + b_lm_off + (uint32_t)(nt * 8 * MSTR + ks * 16) * 2;
                asm volatile("ldmatrix.sync.aligned.m8n8.x2.shared.b16 {%0,%1}, [%2];"
                    : "=r"(bf[nt][0]), "=r"(bf[nt][1]) : "r"(addr));
            }
            #pragma unroll
            for (int mt = 0; mt < 4; mt++)
                #pragma unroll
                for (int nt = 0; nt < 4; nt++) {
                    asm volatile(
                        "mma.sync.aligned.m16n8k16.row.col.f32.bf16.bf16.f32 "
                        "{%0,%1,%2,%3}, {%4,%5,%6,%7}, {%8,%9}, {%0,%1,%2,%3};"
                        : "+f"(acc[mt][nt][0]), "+f"(acc[mt][nt][1]),
                          "+f"(acc[mt][nt][2]), "+f"(acc[mt][nt][3])
                        : "r"(af[mt][0]), "r"(af[mt][1]), "r"(af[mt][2]), "r"(af[mt][3]),
                          "r"(bf[nt][0]), "r"(bf[nt][1]));
                }
        }
        __syncthreads();
    }

    const int row_in = lane >> 2;
    const int col_in = (lane & 3) << 1;
    #pragma unroll
    for (int mt = 0; mt < 4; mt++) {
        #pragma unroll
        for (int nt = 0; nt < 4; nt++) {
            int n = n0 + warp_n * 32 + nt * 8 + col_in;
            float b0 = bias[n], b1 = bias[n + 1];
            #pragma unroll
            for (int half = 0; half < 2; half++) {
                int m = m0 + warp_m * 64 + mt * 16 + row_in + half * 8;
                float2 o;
                o.x = acc[mt][nt][half * 2 + 0] + b0;
                o.y = acc[mt][nt][half * 2 + 1] + b1;
                if (EPI == 1) { o.x = fmaxf(o.x, 0.f); o.y = fmaxf(o.y, 0.f); }
                if (EPI == 2) {
                    float2 rr = *reinterpret_cast<const float2*>(Res + (size_t)m * N + n);
                    o.x += rr.x; o.y += rr.y;
                }
                *reinterpret_cast<float2*>(C + (size_t)m * N + n) = o;
            }
        }
    }
}

// ---------------------------------------------------------------------------
// bf16x3 split-precision MMA GEMM (near-fp32 accuracy):
//   C = (A_hi+A_lo) @ (B_hi+B_lo)^T + bias  ≈ Ahi*Bhi + Ahi*Blo + Alo*Bhi
// Used for the accuracy-critical attn-logits + sampling-offsets GEMM.
// K=256, N=256 shapes (multiples of tile), bias-only epilogue.
// ---------------------------------------------------------------------------
__global__ void __launch_bounds__(256, 2)
mma_gemm_x3(const float* __restrict__ A, const __nv_bfloat16* __restrict__ Bhi,
            const __nv_bfloat16* __restrict__ Blo, const float* __restrict__ bias,
            float* __restrict__ C, int K, int N) {
    __shared__ __nv_bfloat16 AsH[MBM * MSTR];
    __shared__ __nv_bfloat16 AsL[MBM * MSTR];
    __shared__ __nv_bfloat16 BsH[MBN * MSTR];
    __shared__ __nv_bfloat16 BsL[MBN * MSTR];
    const uint32_t ash = smem_to_u32(AsH);
    const uint32_t asl = smem_to_u32(AsL);
    const uint32_t bsh = smem_to_u32(BsH);
    const uint32_t bsl = smem_to_u32(BsL);

    const int tid  = threadIdx.x;
    const int wid  = tid >> 5;
    const int lane = tid & 31;
    const int warp_m = wid >> 2;
    const int warp_n = wid & 3;
    const int m0 = blockIdx.y * MBM;
    const int n0 = blockIdx.x * MBN;

    float acc[4][4][4];
    #pragma unroll
    for (int i = 0; i < 4; i++)
        #pragma unroll
        for (int j = 0; j < 4; j++)
            #pragma unroll
            for (int r = 0; r < 4; r++) acc[i][j][r] = 0.f;

    const int l16 = lane & 15;
    const uint32_t a_lm_off = (uint32_t)((warp_m * 64 + l16) * MSTR + (lane >> 4) * 8) * 2;
    const uint32_t b_lm_off = (uint32_t)((warp_n * 32 + (l16 & 7)) * MSTR + ((l16 >> 3) * 8)) * 2;

    for (int k0 = 0; k0 < K; k0 += MBK) {
        // A tile with hi/lo split
        #pragma unroll
        for (int i = 0; i < 4; i++) {
            int e = i * 256 + tid;
            int r = e >> 3;
            int c = (e & 7) << 2;
            float4 av = *reinterpret_cast<const float4*>(A + (size_t)(m0 + r) * K + k0 + c);
            __nv_bfloat16 hx = __float2bfloat16(av.x);
            __nv_bfloat16 hy = __float2bfloat16(av.y);
            __nv_bfloat16 hz = __float2bfloat16(av.z);
            __nv_bfloat16 hw = __float2bfloat16(av.w);
            __nv_bfloat162 h01; h01.x = hx; h01.y = hy;
            __nv_bfloat162 h23; h23.x = hz; h23.y = hw;
            uint32_t hp0 = *reinterpret_cast<uint32_t*>(&h01);
            uint32_t hp1 = *reinterpret_cast<uint32_t*>(&h23);
            float lx = av.x - __bfloat162float(hx);
            float ly = av.y - __bfloat162float(hy);
            float lz = av.z - __bfloat162float(hz);
            float lw = av.w - __bfloat162float(hw);
            uint32_t lp0, lp1;
            asm("cvt.rn.satfinite.bf16x2.f32 %0, %1, %2;" : "=r"(lp0) : "f"(ly), "f"(lx));
            asm("cvt.rn.satfinite.bf16x2.f32 %0, %1, %2;" : "=r"(lp1) : "f"(lw), "f"(lz));
            uint32_t off = (uint32_t)(r * MSTR + c) * 2;
            asm volatile("st.shared.v2.b32 [%0], {%1, %2};" :: "r"(ash + off), "r"(hp0), "r"(hp1));
            asm volatile("st.shared.v2.b32 [%0], {%1, %2};" :: "r"(asl + off), "r"(lp0), "r"(lp1));
        }
        // B hi/lo tiles
        #pragma unroll
        for (int i = 0; i < 2; i++) {
            int e = i * 256 + tid;
            int r = e >> 2;
            int c = (e & 3) << 3;
            uint4 bh = *reinterpret_cast<const uint4*>(Bhi + (size_t)(n0 + r) * K + k0 + c);
            uint4 bl = *reinterpret_cast<const uint4*>(Blo + (size_t)(n0 + r) * K + k0 + c);
            uint32_t off = (uint32_t)(r * MSTR + c) * 2;
            asm volatile("st.shared.v4.b32 [%0], {%1, %2, %3, %4};"
                :: "r"(bsh + off), "r"(bh.x), "r"(bh.y), "r"(bh.z), "r"(bh.w));
            asm volatile("st.shared.v4.b32 [%0], {%1, %2, %3, %4};"
                :: "r"(bsl + off), "r"(bl.x), "r"(bl.y), "r"(bl.z), "r"(bl.w));
        }
        __syncthreads();

        // 3 passes: (Ahi,Bhi), (Ahi,Blo), (Alo,Bhi)
        #pragma unroll
        for (int pass = 0; pass < 3; pass++) {
            uint32_t abase = (pass == 2) ? asl : ash;
            uint32_t bbase = (pass == 1) ? bsl : bsh;
            #pragma unroll
            for (int ks = 0; ks < 2; ks++) {
                uint32_t af[4][4];
                #pragma unroll
                for (int mt = 0; mt < 4; mt++) {
                    uint32_t addr = abase + a_lm_off + (uint32_t)(mt * 16 * MSTR + ks * 16) * 2;
                    asm volatile("ldmatrix.sync.aligned.m8n8.x4.shared.b16 {%0,%1,%2,%3}, [%4];"
                        : "=r"(af[mt][0]), "=r"(af[mt][1]), "=r"(af[mt][2]), "=r"(af[mt][3])
                        : "r"(addr));
                }
                uint32_t bf[4][2];
                #pragma unroll
                for (int nt = 0; nt < 4; nt++) {
                    uint32_t addr = bbase + b_lm_off + (uint32_t)(nt * 8 * MSTR + ks * 16) * 2;
                    asm volatile("ldmatrix.sync.aligned.m8n8.x2.shared.b16 {%0,%1}, [%2];"
                        : "=r"(bf[nt][0]), "=r"(bf[nt][1]) : "r"(addr));
                }
                #pragma unroll
                for (int mt = 0; mt < 4; mt++)
                    #pragma unroll
                    for (int nt = 0; nt < 4; nt++) {
                        asm volatile(
                            "mma.sync.aligned.m16n8k16.row.col.f32.bf16.bf16.f32 "
                            "{%0,%1,%2,%3}, {%4,%5,%6,%7}, {%8,%9}, {%0,%1,%2,%3};"
                            : "+f"(acc[mt][nt][0]), "+f"(acc[mt][nt][1]),
                              "+f"(acc[mt][nt][2]), "+f"(acc[mt][nt][3])
                            : "r"(af[mt][0]), "r"(af[mt][1]), "r"(af[mt][2]), "r"(af[mt][3]),
                              "r"(bf[nt][0]), "r"(bf[nt][1]));
                    }
            }
        }
        __syncthreads();
    }

    const int row_in = lane >> 2;
    const int col_in = (lane & 3) << 1;
    #pragma unroll
    for (int mt = 0; mt < 4; mt++) {
        #pragma unroll
        for (int nt = 0; nt < 4; nt++) {
            int n = n0 + warp_n * 32 + nt * 8 + col_in;
            float b0 = bias[n], b1 = bias[n + 1];
            #pragma unroll
            for (int half = 0; half < 2; half++) {
                int m = m0 + warp_m * 64 + mt * 16 + row_in + half * 8;
                float2 o;
                o.x = acc[mt][nt][half * 2 + 0] + b0;
                o.y = acc[mt][nt][half * 2 + 1] + b1;
                *reinterpret_cast<float2*>(C + (size_t)m * N + n) = o;
            }
        }
    }
}

// ---------------------------------------------------------------------------
// A-resident K=256 GEMM for the big v-projection (bf16 output)
// ---------------------------------------------------------------------------
#define ASTRIDE 264   // 132 words; 132 % 8 == 4 -> conflict-free ldmatrix
#define K256 256
#define KSMEM_A_BYTES (128 * ASTRIDE * 2)
#define KSMEM_TOTAL   (KSMEM_A_BYTES + 128 * MSTR * 2)

__global__ void __launch_bounds__(256, 2)
mma_k256_vproj(const float* __restrict__ A, const __nv_bfloat16* __restrict__ B,
               const float* __restrict__ bias, __nv_bfloat16* __restrict__ C) {
    extern __shared__ __nv_bfloat16 sm[];
    __nv_bfloat16* As = sm;
    __nv_bfloat16* Bs = sm + 128 * ASTRIDE;
    const uint32_t as_base = smem_to_u32(As);
    const uint32_t bs_base = smem_to_u32(Bs);

    const int tid  = threadIdx.x;
    const int wid  = tid >> 5;
    const int lane = tid & 31;
    const int warp_m = wid >> 2;
    const int warp_n = wid & 3;
    const int m0 = blockIdx.x * 128;

    #pragma unroll
    for (int i = 0; i < 32; i++) {
        int e = i * 256 + tid;
        int r = e >> 6;
        int c = (e & 63) << 2;
        float4 av = *reinterpret_cast<const float4*>(A + (size_t)(m0 + r) * K256 + c);
        uint32_t p0, p1;
        asm("cvt.rn.satfinite.bf16x2.f32 %0, %1, %2;" : "=r"(p0) : "f"(av.y), "f"(av.x));
        asm("cvt.rn.satfinite.bf16x2.f32 %0, %1, %2;" : "=r"(p1) : "f"(av.w), "f"(av.z));
        uint32_t addr = as_base + (uint32_t)(r * ASTRIDE + c) * 2;
        asm volatile("st.shared.v2.b32 [%0], {%1, %2};" :: "r"(addr), "r"(p0), "r"(p1));
    }
    __syncthreads();

    const int l16 = lane & 15;
    const uint32_t a_lm_off = (uint32_t)((warp_m * 64 + l16) * ASTRIDE + (lane >> 4) * 8) * 2;
    const uint32_t b_lm_off = (uint32_t)((warp_n * 32 + (l16 & 7)) * MSTR + ((l16 >> 3) * 8)) * 2;
    const int row_in = lane >> 2;
    const int col_in = (lane & 3) << 1;

    for (int nh = 0; nh < 2; nh++) {
        const int n0 = nh * 128;
        float acc[4][4][4];
        #pragma unroll
        for (int i = 0; i < 4; i++)
            #pragma unroll
            for (int j = 0; j < 4; j++)
                #pragma unroll
                for (int r = 0; r < 4; r++) acc[i][j][r] = 0.f;

        for (int ks8 = 0; ks8 < 8; ks8++) {
            #pragma unroll
            for (int i = 0; i < 2; i++) {
                int e = i * 256 + tid;
                int r = e >> 2;
                int c = (e & 3) << 3;
                uint4 bv = *reinterpret_cast<const uint4*>(
                    B + (size_t)(n0 + r) * K256 + ks8 * 32 + c);
                uint32_t addr = bs_base + (uint32_t)(r * MSTR + c) * 2;
                asm volatile("st.shared.v4.b32 [%0], {%1, %2, %3, %4};"
                    :: "r"(addr), "r"(bv.x), "r"(bv.y), "r"(bv.z), "r"(bv.w));
            }
            __syncthreads();
            #pragma unroll
            for (int sub = 0; sub < 2; sub++) {
                int kk = ks8 * 32 + sub * 16;
                uint32_t af[4][4];
                #pragma unroll
                for (int mt = 0; mt < 4; mt++) {
                    uint32_t addr = as_base + a_lm_off + (uint32_t)(mt * 16 * ASTRIDE + kk) * 2;
                    asm volatile("ldmatrix.sync.aligned.m8n8.x4.shared.b16 {%0,%1,%2,%3}, [%4];"
                        : "=r"(af[mt][0]), "=r"(af[mt][1]), "=r"(af[mt][2]), "=r"(af[mt][3])
                        : "r"(addr));
                }
                uint32_t bf[4][2];
                #pragma unroll
                for (int nt = 0; nt < 4; nt++) {
                    uint32_t addr = bs_base + b_lm_off + (uint32_t)(nt * 8 * MSTR + sub * 16) * 2;
                    asm volatile("ldmatrix.sync.aligned.m8n8.x2.shared.b16 {%0,%1}, [%2];"
                        : "=r"(bf[nt][0]), "=r"(bf[nt][1]) : "r"(addr));
                }
                #pragma unroll
                for (int mt = 0; mt < 4; mt++)
                    #pragma unroll
                    for (int nt = 0; nt < 4; nt++) {
                        asm volatile(
                            "mma.sync.aligned.m16n8k16.row.col.f32.bf16.bf16.f32 "
                            "{%0,%1,%2,%3}, {%4,%5,%6,%7}, {%8,%9}, {%0,%1,%2,%3};"
                            : "+f"(acc[mt][nt][0]), "+f"(acc[mt][nt][1]),
                              "+f"(acc[mt][nt][2]), "+f"(acc[mt][nt][3])
                            : "r"(af[mt][0]), "r"(af[mt][1]), "r"(af[mt][2]), "r"(af[mt][3]),
                              "r"(bf[nt][0]), "r"(bf[nt][1]));
                    }
            }
            __syncthreads();
        }
        #pragma unroll
        for (int mt = 0; mt < 4; mt++) {
            #pragma unroll
            for (int nt = 0; nt < 4; nt++) {
                int n = n0 + warp_n * 32 + nt * 8 + col_in;
                float b0 = bias[n], b1 = bias[n + 1];
                #pragma unroll
                for (int half = 0; half < 2; half++) {
                    int m = m0 + warp_m * 64 + mt * 16 + row_in + half * 8;
                    float ox = acc[mt][nt][half * 2 + 0] + b0;
                    float oy = acc[mt][nt][half * 2 + 1] + b1;
                    uint32_t pr;
                    asm("cvt.rn.satfinite.bf16x2.f32 %0, %1, %2;" : "=r"(pr) : "f"(oy), "f"(ox));
                    *reinterpret_cast<uint32_t*>(C + (size_t)m * K256 + n) = pr;
                }
            }
        }
    }
}

// ---------------------------------------------------------------------------
// Weight prep kernels
// ---------------------------------------------------------------------------
__global__ void f2bf_kernel(const float* __restrict__ src, __nv_bfloat16* __restrict__ dst, int n) {
    int i = blockIdx.x * 256 + threadIdx.x;
    if (i < n) dst[i] = __float2bfloat16(src[i]);
}

__global__ void pack_wab(const float* __restrict__ Wa, const float* __restrict__ Wb,
                         const float* __restrict__ ba, const float* __restrict__ bb,
                         __nv_bfloat16* __restrict__ Whi, __nv_bfloat16* __restrict__ Wlo,
                         float* __restrict__ bab) {
    int row = blockIdx.x;
    int col = threadIdx.x;
    float w = 0.f;
    if (row < 200)      w = Wa[row * DIM + col];
    else if (row < 240) w = Wb[(row - 200) * DIM + col];
    __nv_bfloat16 hi = __float2bfloat16(w);
    Whi[row * DIM + col] = hi;
    Wlo[row * DIM + col] = __float2bfloat16(w - __bfloat162float(hi));
    if (col == 0) {
        float b = 0.f;
        if (row < 200)      b = ba[row];
        else if (row < 240) b = bb[row - 200];
        bab[row] = b;
    }
}

// ---------------------------------------------------------------------------
// fp32 SGEMM (tiny K=8 first pos-MLP layer only)
// ---------------------------------------------------------------------------
#define BM 64
#define BN 64
#define BKT 16

__global__ void sgemm_k8_relu(const float* __restrict__ A, const float* __restrict__ B,
                              const float* __restrict__ bias, float* __restrict__ C,
                              int M, int N, int K) {
    __shared__ float As[BKT][BM];
    __shared__ float Bs[BKT][BN];
    const int tid  = threadIdx.x;
    const int brow = blockIdx.y * BM;
    const int bcol = blockIdx.x * BN;
    const int tx = tid & 15;
    const int ty = tid >> 4;
    const int lr = tid >> 2;
    const int lk = (tid & 3) << 2;

    float acc[4][4] = {};
    for (int k0 = 0; k0 < K; k0 += BKT) {
        #pragma unroll
        for (int i = 0; i < 4; i++) {
            int k = k0 + lk + i;
            As[lk + i][lr] = (k < K) ? A[(size_t)(brow + lr) * K + k] : 0.f;
            Bs[lk + i][lr] = (k < K) ? B[(size_t)(bcol + lr) * K + k] : 0.f;
        }
        __syncthreads();
        #pragma unroll
        for (int kk = 0; kk < BKT; kk++) {
            float4 a4 = *reinterpret_cast<const float4*>(&As[kk][ty << 2]);
            float4 b4 = *reinterpret_cast<const float4*>(&Bs[kk][tx << 2]);
            float ar[4] = {a4.x, a4.y, a4.z, a4.w};
            float br[4] = {b4.x, b4.y, b4.z, b4.w};
            #pragma unroll
            for (int i = 0; i < 4; i++)
                #pragma unroll
                for (int j = 0; j < 4; j++)
                    acc[i][j] = fmaf(ar[i], br[j], acc[i][j]);
        }
        __syncthreads();
    }
    #pragma unroll
    for (int i = 0; i < 4; i++) {
        int r = brow + (ty << 2) + i;
        #pragma unroll
        for (int j = 0; j < 4; j++) {
            int c = bcol + (tx << 2) + j;
            C[(size_t)r * N + c] = fmaxf(acc[i][j] + bias[c], 0.f);
        }
    }
}

// ---------------------------------------------------------------------------
// Deformable bilinear sampling with fused softmax; v in bf16.
// ao layout: [n][0..199] attn logits (h*25+p), [n][200..239] offsets (h*5+j)
// ---------------------------------------------------------------------------
__global__ void sample_kernel(const float* __restrict__ rw,
                              const float* __restrict__ ao,
                              const __nv_bfloat16* __restrict__ v,
                              float* __restrict__ out) {
    int n    = blockIdx.x;
    int h    = threadIdx.x >> 5;
    int lane = threadIdx.x & 31;

    const float* aon = ao + (size_t)n * DIM;
    float logit = (lane < PP) ? aon[h * PP + lane] : -1e30f;
    float mx = logit;
    #pragma unroll
    for (int o = 16; o; o >>= 1) mx = fmaxf(mx, __shfl_xor_sync(0xffffffffu, mx, o));
    float e = (lane < PP) ? expf(logit - mx) : 0.f;
    float s = e;
    #pragma unroll
    for (int o = 16; o; o >>= 1) s += __shfl_xor_sync(0xffffffffu, s, o);
    float myattn = e / s;

    const float* rwn = rw + (size_t)n * 8;
    float rw0 = rwn[0], rw1 = rwn[1], rw3 = rwn[3], rw4 = rwn[4], rw6 = rwn[6];
    const float* offn = aon + 200 + h * 5;
    float o0 = offn[0], o1 = offn[1], o2 = offn[2], o3 = offn[3], o4 = offn[4];

    float cx = rw0 + o0 * 0.125f * rw3;
    float cy = rw1 + o1 * 0.125f * rw4;
    float sx = fmaxf(rw3 + o2 * 0.125f * rw3, 0.f);
    float sy = fmaxf(rw4 + o3 * 0.125f * rw4, 0.f);
    float ang = (rw6 + o4 * (1.0f / 16.0f)) * 6.2831853071795864769f;
    float sth, cth;
    sincosf(ang, &sth, &cth);

    const __nv_bfloat16* vh = v + h * HD + lane;

    float acc = 0.f;
    #pragma unroll
    for (int p = 0; p < PP; p++) {
        int a = p / 5, b = p % 5;
        float gx = sx * (float)(b - 2) * 0.2f;
        float gy = sy * (float)(a - 2) * 0.2f;
        float lx = cx + gx * cth - gy * sth;
        float ly = cy + gx * sth + gy * cth;
        float x = lx * (float)WW - 0.5f;
        float y = ly * (float)HH - 0.5f;
        float x0f = floorf(x), y0f = floorf(y);
        float fx = x - x0f, fy = y - y0f;
        int x0 = (int)x0f, y0 = (int)y0f;
        float ap = __shfl_sync(0xffffffffu, myattn, p);
        #pragma unroll
        for (int c = 0; c < 4; c++) {
            int dx = c & 1, dy = c >> 1;
            int xi = x0 + dx, yi = y0 + dy;
            float wx = dx ? fx : (1.f - fx);
            float wy = dy ? fy : (1.f - fy);
            bool valid = (xi >= 0) && (xi <= WW - 1) && (yi >= 0) && (yi <= HH - 1);
            if (valid) {
                float g = __bfloat162float(vh[(size_t)(yi * WW + xi) * DIM]);
                acc = fmaf(ap * wx * wy, g, acc);
            }
        }
    }
    out[(size_t)n * DIM + h * HD + lane] = acc;
}

// ---------------------------------------------------------------------------
// LayerNorm (residual add + LN)
// ---------------------------------------------------------------------------
__global__ void ln_kernel(const float* __restrict__ A, const float* __restrict__ Bb,
                          const float* __restrict__ gamma, const float* __restrict__ beta,
                          float* __restrict__ O) {
    int n = blockIdx.x;
    int c = threadIdx.x;
    float x = A[(size_t)n * DIM + c] + Bb[(size_t)n * DIM + c];
    float s = x, sq = x * x;
    #pragma unroll
    for (int o = 16; o; o >>= 1) {
        s  += __shfl_xor_sync(0xffffffffu, s, o);
        sq += __shfl_xor_sync(0xffffffffu, sq, o);
    }
    __shared__ float sh_s[8], sh_q[8];
    if ((c & 31) == 0) { sh_s[c >> 5] = s; sh_q[c >> 5] = sq; }
    __syncthreads();
    float ts = 0.f, tq = 0.f;
    #pragma unroll
    for (int i = 0; i < 8; i++) { ts += sh_s[i]; tq += sh_q[i]; }
    float mean = ts * (1.0f / (float)DIM);
    float var  = tq * (1.0f / (float)DIM) - mean * mean;
    var = fmaxf(var, 0.f);
    float inv = rsqrtf(var + 1e-5f);
    O[(size_t)n * DIM + c] = (x - mean) * inv * gamma[c] + beta[c];
}

// ---------------------------------------------------------------------------
// Host orchestration
// ---------------------------------------------------------------------------
extern "C" void kernel_launch(void* const* d_in, const int* in_sizes, int n_in,
                              void* d_out, int out_size) {
    const float* query = (const float*)d_in[0];
    const float* memory = (const float*)d_in[1];
    const float* ref_w  = (const float*)d_in[2];
    const float* Wp1 = (const float*)d_in[5];
    const float* bp1 = (const float*)d_in[6];
    const float* Wp2 = (const float*)d_in[7];
    const float* bp2 = (const float*)d_in[8];
    const float* Wp3 = (const float*)d_in[9];
    const float* bp3 = (const float*)d_in[10];
    const float* Wv  = (const float*)d_in[11];
    const float* bv  = (const float*)d_in[12];
    const float* Wa  = (const float*)d_in[13];
    const float* ba  = (const float*)d_in[14];
    const float* Wb  = (const float*)d_in[15];
    const float* bb  = (const float*)d_in[16];
    const float* Wo  = (const float*)d_in[17];
    const float* bo  = (const float*)d_in[18];
    const float* W1  = (const float*)d_in[19];
    const float* b1  = (const float*)d_in[20];
    const float* W2  = (const float*)d_in[21];
    const float* b2  = (const float*)d_in[22];
    const float* g2  = (const float*)d_in[23];
    const float* be2 = (const float*)d_in[24];
    const float* g3  = (const float*)d_in[25];
    const float* be3 = (const float*)d_in[26];
    float* out = (float*)d_out;

    __nv_bfloat16 *v_bf, *Wv_bf, *Wo_bf, *W1_bf, *W2_bf, *Wp2_bf, *Wp3_bf, *Wab_hi, *Wab_lo;
    float *q, *buf1, *buf2, *smp, *xq, *bab;
    cudaGetSymbolAddress((void**)&v_bf,   g_v_bf);
    cudaGetSymbolAddress((void**)&q,      g_q);
    cudaGetSymbolAddress((void**)&buf1,   g_buf1);
    cudaGetSymbolAddress((void**)&buf2,   g_buf2);
    cudaGetSymbolAddress((void**)&smp,    g_smp);
    cudaGetSymbolAddress((void**)&xq,     g_xq);
    cudaGetSymbolAddress((void**)&Wv_bf,  g_Wv_bf);
    cudaGetSymbolAddress((void**)&Wo_bf,  g_Wo_bf);
    cudaGetSymbolAddress((void**)&W1_bf,  g_W1_bf);
    cudaGetSymbolAddress((void**)&W2_bf,  g_W2_bf);
    cudaGetSymbolAddress((void**)&Wp2_bf, g_Wp2_bf);
    cudaGetSymbolAddress((void**)&Wp3_bf, g_Wp3_bf);
    cudaGetSymbolAddress((void**)&Wab_hi, g_Wab_hi);
    cudaGetSymbolAddress((void**)&Wab_lo, g_Wab_lo);
    cudaGetSymbolAddress((void**)&bab,    g_bab);

    cudaFuncSetAttribute(mma_k256_vproj, cudaFuncAttributeMaxDynamicSharedMemorySize, KSMEM_TOTAL);

    // 0) Weight prep
    f2bf_kernel<<<(DIM * DIM + 255) / 256, 256>>>(Wv, Wv_bf, DIM * DIM);
    f2bf_kernel<<<(DIM * DIM + 255) / 256, 256>>>(Wo, Wo_bf, DIM * DIM);
    f2bf_kernel<<<(DFF * DIM + 255) / 256, 256>>>(W1, W1_bf, DFF * DIM);
    f2bf_kernel<<<(DIM * DFF + 255) / 256, 256>>>(W2, W2_bf, DIM * DFF);
    f2bf_kernel<<<(DIM * DIM + 255) / 256, 256>>>(Wp2, Wp2_bf, DIM * DIM);
    f2bf_kernel<<<(DIM * DIM + 255) / 256, 256>>>(Wp3, Wp3_bf, DIM * DIM);
    pack_wab<<<DIM, DIM>>>(Wa, Wb, ba, bb, Wab_hi, Wab_lo, bab);

    // 1) Positional MLP: layer1 fp32 (K=8), layers 2/3 bf16 MMA (qp tiny vs query)
    sgemm_k8_relu<<<dim3(DIM / BN, NQ / BM), 256>>>(ref_w, Wp1, bp1, buf1, NQ, DIM, 8);
    mma_gemm<1><<<dim3(2, NQ / MBM), 256>>>(buf1, Wp2_bf, bp2, nullptr, buf2, DIM, DIM);
    mma_gemm<2><<<dim3(2, NQ / MBM), 256>>>(buf2, Wp3_bf, bp3, query, q, DIM, DIM);

    // 2) Value projection: A-resident K=256 kernel, bf16 output
    mma_k256_vproj<<<HWSZ / 128, 256, KSMEM_TOTAL>>>(memory, Wv_bf, bv, v_bf);

    // 3) Attn-logits + offsets GEMM in bf16x3 (near-fp32; locations are sensitive)
    mma_gemm_x3<<<dim3(2, NQ / MBM), 256>>>(q, Wab_hi, Wab_lo, bab, buf1, DIM, DIM);

    // 4) Sampling (fused softmax), bf16 v
    sample_kernel<<<NQ, 256>>>(ref_w, buf1, v_bf, smp);

    // 5) Output projection + residual LN
    mma_gemm<0><<<dim3(2, NQ / MBM), 256>>>(smp, Wo_bf, bo, nullptr, buf2, DIM, DIM);
    ln_kernel<<<NQ, 256>>>(query, buf2, g2, be2, xq);

    // 6) FFN + final LN
    mma_gemm<1><<<dim3(DFF / MBN, NQ / MBM), 256>>>(xq, W1_bf, b1, nullptr, buf1, DIM, DFF);
    mma_gemm<0><<<dim3(2, NQ / MBM), 256>>>(buf1, W2_bf, b2, nullptr, buf2, DFF, DIM);
    ln_kernel<<<NQ, 256>>>(xq, buf2, g3, be3, out);
}

// round 6
// speedup vs baseline: 4.2886x; 1.0938x over previous
#include <cuda_runtime.h>
#include <cuda_bf16.h>
#include <math.h>
#include <cstdint>

// Problem constants
#define NQ   8192
#define DIM  256
#define NH   8
#define HD   32
#define PP   25
#define HH   512
#define WW   512
#define HWSZ (HH * WW)
#define DFF  1024

// ---------------------------------------------------------------------------
// Scratch (device globals)
// ---------------------------------------------------------------------------
__device__ __nv_bfloat16 g_v_bf[(size_t)NH * HWSZ * HD];  // head-major value tensor
__device__ float g_q[NQ * DIM];
__device__ float g_buf1[NQ * DFF];
__device__ float g_buf2[NQ * DIM];
__device__ float g_smp[NQ * DIM];
__device__ float g_xq[NQ * DIM];
__device__ __nv_bfloat16 g_Wv_bf[DIM * DIM];
__device__ __nv_bfloat16 g_Wo_bf[DIM * DIM];
__device__ __nv_bfloat16 g_W1_bf[DFF * DIM];
__device__ __nv_bfloat16 g_W2_bf[DIM * DFF];
__device__ __nv_bfloat16 g_Wp2_bf[DIM * DIM];
__device__ __nv_bfloat16 g_Wp3_bf[DIM * DIM];
__device__ __nv_bfloat16 g_Wab_hi[DIM * DIM];
__device__ __nv_bfloat16 g_Wab_lo[DIM * DIM];
__device__ float g_bab[DIM];

__device__ __forceinline__ uint32_t smem_to_u32(const void* p) {
    uint32_t a;
    asm("{ .reg .u64 t; cvta.to.shared.u64 t, %1; cvt.u32.u64 %0, t; }" : "=r"(a) : "l"(p));
    return a;
}
#define CP_ASYNC16(dst, src) \
    asm volatile("cp.async.cg.shared.global [%0], [%1], 16;" :: "r"(dst), "l"(src))
#define CP_COMMIT() asm volatile("cp.async.commit_group;" ::: "memory")
#define CP_WAIT0()  asm volatile("cp.async.wait_group 0;" ::: "memory")

#define MBM 128
#define MBN 128
#define MBK 32
#define MSTR 40   // smem row stride: 20 words, 20 % 8 == 4 -> conflict-free ldmatrix

// ---------------------------------------------------------------------------
// Generic warp-MMA bf16 GEMM:  C[M,N] = A[fp32,MxK] @ B[bf16,NxK]^T
// EPI: 0=+bias, 1=+bias+relu, 2=+bias+Res
// ---------------------------------------------------------------------------
template <int EPI>
__global__ void __launch_bounds__(256, 2)
mma_gemm(const float* __restrict__ A, const __nv_bfloat16* __restrict__ B,
         const float* __restrict__ bias, const float* __restrict__ Res,
         float* __restrict__ C, int K, int N) {
    __shared__ __nv_bfloat16 As[MBM * MSTR];
    __shared__ __nv_bfloat16 Bs[MBN * MSTR];
    const uint32_t as_base = smem_to_u32(As);
    const uint32_t bs_base = smem_to_u32(Bs);

    const int tid  = threadIdx.x;
    const int wid  = tid >> 5;
    const int lane = tid & 31;
    const int warp_m = wid >> 2;
    const int warp_n = wid & 3;
    const int m0 = blockIdx.y * MBM;
    const int n0 = blockIdx.x * MBN;

    float acc[4][4][4];
    #pragma unroll
    for (int i = 0; i < 4; i++)
        #pragma unroll
        for (int j = 0; j < 4; j++)
            #pragma unroll
            for (int r = 0; r < 4; r++) acc[i][j][r] = 0.f;

    const int l16 = lane & 15;
    const uint32_t a_lm_off = (uint32_t)((warp_m * 64 + l16) * MSTR + (lane >> 4) * 8) * 2;
    const uint32_t b_lm_off = (uint32_t)((warp_n * 32 + (l16 & 7)) * MSTR + ((l16 >> 3) * 8)) * 2;

    for (int k0 = 0; k0 < K; k0 += MBK) {
        #pragma unroll
        for (int i = 0; i < 4; i++) {
            int e = i * 256 + tid;
            int r = e >> 3;
            int c = (e & 7) << 2;
            float4 av = *reinterpret_cast<const float4*>(A + (size_t)(m0 + r) * K + k0 + c);
            uint32_t p0, p1;
            asm("cvt.rn.satfinite.bf16x2.f32 %0, %1, %2;" : "=r"(p0) : "f"(av.y), "f"(av.x));
            asm("cvt.rn.satfinite.bf16x2.f32 %0, %1, %2;" : "=r"(p1) : "f"(av.w), "f"(av.z));
            uint32_t addr = as_base + (uint32_t)(r * MSTR + c) * 2;
            asm volatile("st.shared.v2.b32 [%0], {%1, %2};" :: "r"(addr), "r"(p0), "r"(p1));
        }
        #pragma unroll
        for (int i = 0; i < 2; i++) {
            int e = i * 256 + tid;
            int r = e >> 2;
            int c = (e & 3) << 3;
            uint4 bv = *reinterpret_cast<const uint4*>(B + (size_t)(n0 + r) * K + k0 + c);
            uint32_t addr = bs_base + (uint32_t)(r * MSTR + c) * 2;
            asm volatile("st.shared.v4.b32 [%0], {%1, %2, %3, %4};"
                :: "r"(addr), "r"(bv.x), "r"(bv.y), "r"(bv.z), "r"(bv.w));
        }
        __syncthreads();

        #pragma unroll
        for (int ks = 0; ks < 2; ks++) {
            uint32_t af[4][4];
            #pragma unroll
            for (int mt = 0; mt < 4; mt++) {
                uint32_t addr = as_base + a_lm_off + (uint32_t)(mt * 16 * MSTR + ks * 16) * 2;
                asm volatile("ldmatrix.sync.aligned.m8n8.x4.shared.b16 {%0,%1,%2,%3}, [%4];"
                    : "=r"(af[mt][0]), "=r"(af[mt][1]), "=r"(af[mt][2]), "=r"(af[mt][3])
                    : "r"(addr));
            }
            uint32_t bf[4][2];
            #pragma unroll
            for (int nt = 0; nt < 4; nt++) {
                uint32_t addr = bs_base + b_lm_off + (uint32_t)(nt * 8 * MSTR + ks * 16) * 2;
                asm volatile("ldmatrix.sync.aligned.m8n8.x2.shared.b16 {%0,%1}, [%2];"
                    : "=r"(bf[nt][0]), "=r"(bf[nt][1]) : "r"(addr));
            }
            #pragma unroll
            for (int mt = 0; mt < 4; mt++)
                #pragma unroll
                for (int nt = 0; nt < 4; nt++) {
                    asm volatile(
                        "mma.sync.aligned.m16n8k16.row.col.f32.bf16.bf16.f32 "
                        "{%0,%1,%2,%3}, {%4,%5,%6,%7}, {%8,%9}, {%0,%1,%2,%3};"
                        : "+f"(acc[mt][nt][0]), "+f"(acc[mt][nt][1]),
                          "+f"(acc[mt][nt][2]), "+f"(acc[mt][nt][3])
                        : "r"(af[mt][0]), "r"(af[mt][1]), "r"(af[mt][2]), "r"(af[mt][3]),
                          "r"(bf[nt][0]), "r"(bf[nt][1]));
                }
        }
        __syncthreads();
    }

    const int row_in = lane >> 2;
    const int col_in = (lane & 3) << 1;
    #pragma unroll
    for (int mt = 0; mt < 4; mt++) {
        #pragma unroll
        for (int nt = 0; nt < 4; nt++) {
            int n = n0 + warp_n * 32 + nt * 8 + col_in;
            float b0 = bias[n], b1 = bias[n + 1];
            #pragma unroll
            for (int half = 0; half < 2; half++) {
                int m = m0 + warp_m * 64 + mt * 16 + row_in + half * 8;
                float2 o;
                o.x = acc[mt][nt][half * 2 + 0] + b0;
                o.y = acc[mt][nt][half * 2 + 1] + b1;
                if (EPI == 1) { o.x = fmaxf(o.x, 0.f); o.y = fmaxf(o.y, 0.f); }
                if (EPI == 2) {
                    float2 rr = *reinterpret_cast<const float2*>(Res + (size_t)m * N + n);
                    o.x += rr.x; o.y += rr.y;
                }
                *reinterpret_cast<float2*>(C + (size_t)m * N + n) = o;
            }
        }
    }
}

// ---------------------------------------------------------------------------
// bf16x3 split-precision MMA GEMM (near-fp32): attn-logits + offsets GEMM
// ---------------------------------------------------------------------------
__global__ void __launch_bounds__(256, 2)
mma_gemm_x3(const float* __restrict__ A, const __nv_bfloat16* __restrict__ Bhi,
            const __nv_bfloat16* __restrict__ Blo, const float* __restrict__ bias,
            float* __restrict__ C, int K, int N) {
    __shared__ __nv_bfloat16 AsH[MBM * MSTR];
    __shared__ __nv_bfloat16 AsL[MBM * MSTR];
    __shared__ __nv_bfloat16 BsH[MBN * MSTR];
    __shared__ __nv_bfloat16 BsL[MBN * MSTR];
    const uint32_t ash = smem_to_u32(AsH);
    const uint32_t asl = smem_to_u32(AsL);
    const uint32_t bsh = smem_to_u32(BsH);
    const uint32_t bsl = smem_to_u32(BsL);

    const int tid  = threadIdx.x;
    const int wid  = tid >> 5;
    const int lane = tid & 31;
    const int warp_m = wid >> 2;
    const int warp_n = wid & 3;
    const int m0 = blockIdx.y * MBM;
    const int n0 = blockIdx.x * MBN;

    float acc[4][4][4];
    #pragma unroll
    for (int i = 0; i < 4; i++)
        #pragma unroll
        for (int j = 0; j < 4; j++)
            #pragma unroll
            for (int r = 0; r < 4; r++) acc[i][j][r] = 0.f;

    const int l16 = lane & 15;
    const uint32_t a_lm_off = (uint32_t)((warp_m * 64 + l16) * MSTR + (lane >> 4) * 8) * 2;
    const uint32_t b_lm_off = (uint32_t)((warp_n * 32 + (l16 & 7)) * MSTR + ((l16 >> 3) * 8)) * 2;

    for (int k0 = 0; k0 < K; k0 += MBK) {
        #pragma unroll
        for (int i = 0; i < 4; i++) {
            int e = i * 256 + tid;
            int r = e >> 3;
            int c = (e & 7) << 2;
            float4 av = *reinterpret_cast<const float4*>(A + (size_t)(m0 + r) * K + k0 + c);
            __nv_bfloat16 hx = __float2bfloat16(av.x);
            __nv_bfloat16 hy = __float2bfloat16(av.y);
            __nv_bfloat16 hz = __float2bfloat16(av.z);
            __nv_bfloat16 hw = __float2bfloat16(av.w);
            __nv_bfloat162 h01; h01.x = hx; h01.y = hy;
            __nv_bfloat162 h23; h23.x = hz; h23.y = hw;
            uint32_t hp0 = *reinterpret_cast<uint32_t*>(&h01);
            uint32_t hp1 = *reinterpret_cast<uint32_t*>(&h23);
            float lx = av.x - __bfloat162float(hx);
            float ly = av.y - __bfloat162float(hy);
            float lz = av.z - __bfloat162float(hz);
            float lw = av.w - __bfloat162float(hw);
            uint32_t lp0, lp1;
            asm("cvt.rn.satfinite.bf16x2.f32 %0, %1, %2;" : "=r"(lp0) : "f"(ly), "f"(lx));
            asm("cvt.rn.satfinite.bf16x2.f32 %0, %1, %2;" : "=r"(lp1) : "f"(lw), "f"(lz));
            uint32_t off = (uint32_t)(r * MSTR + c) * 2;
            asm volatile("st.shared.v2.b32 [%0], {%1, %2};" :: "r"(ash + off), "r"(hp0), "r"(hp1));
            asm volatile("st.shared.v2.b32 [%0], {%1, %2};" :: "r"(asl + off), "r"(lp0), "r"(lp1));
        }
        #pragma unroll
        for (int i = 0; i < 2; i++) {
            int e = i * 256 + tid;
            int r = e >> 2;
            int c = (e & 3) << 3;
            uint4 bh = *reinterpret_cast<const uint4*>(Bhi + (size_t)(n0 + r) * K + k0 + c);
            uint4 bl = *reinterpret_cast<const uint4*>(Blo + (size_t)(n0 + r) * K + k0 + c);
            uint32_t off = (uint32_t)(r * MSTR + c) * 2;
            asm volatile("st.shared.v4.b32 [%0], {%1, %2, %3, %4};"
                :: "r"(bsh + off), "r"(bh.x), "r"(bh.y), "r"(bh.z), "r"(bh.w));
            asm volatile("st.shared.v4.b32 [%0], {%1, %2, %3, %4};"
                :: "r"(bsl + off), "r"(bl.x), "r"(bl.y), "r"(bl.z), "r"(bl.w));
        }
        __syncthreads();

        #pragma unroll
        for (int pass = 0; pass < 3; pass++) {
            uint32_t abase = (pass == 2) ? asl : ash;
            uint32_t bbase = (pass == 1) ? bsl : bsh;
            #pragma unroll
            for (int ks = 0; ks < 2; ks++) {
                uint32_t af[4][4];
                #pragma unroll
                for (int mt = 0; mt < 4; mt++) {
                    uint32_t addr = abase + a_lm_off + (uint32_t)(mt * 16 * MSTR + ks * 16) * 2;
                    asm volatile("ldmatrix.sync.aligned.m8n8.x4.shared.b16 {%0,%1,%2,%3}, [%4];"
                        : "=r"(af[mt][0]), "=r"(af[mt][1]), "=r"(af[mt][2]), "=r"(af[mt][3])
                        : "r"(addr));
                }
                uint32_t bf[4][2];
                #pragma unroll
                for (int nt = 0; nt < 4; nt++) {
                    uint32_t addr = bbase + b_lm_off + (uint32_t)(nt * 8 * MSTR + ks * 16) * 2;
                    asm volatile("ldmatrix.sync.aligned.m8n8.x2.shared.b16 {%0,%1}, [%2];"
                        : "=r"(bf[nt][0]), "=r"(bf[nt][1]) : "r"(addr));
                }
                #pragma unroll
                for (int mt = 0; mt < 4; mt++)
                    #pragma unroll
                    for (int nt = 0; nt < 4; nt++) {
                        asm volatile(
                            "mma.sync.aligned.m16n8k16.row.col.f32.bf16.bf16.f32 "
                            "{%0,%1,%2,%3}, {%4,%5,%6,%7}, {%8,%9}, {%0,%1,%2,%3};"
                            : "+f"(acc[mt][nt][0]), "+f"(acc[mt][nt][1]),
                              "+f"(acc[mt][nt][2]), "+f"(acc[mt][nt][3])
                            : "r"(af[mt][0]), "r"(af[mt][1]), "r"(af[mt][2]), "r"(af[mt][3]),
                              "r"(bf[nt][0]), "r"(bf[nt][1]));
                    }
            }
        }
        __syncthreads();
    }

    const int row_in = lane >> 2;
    const int col_in = (lane & 3) << 1;
    #pragma unroll
    for (int mt = 0; mt < 4; mt++) {
        #pragma unroll
        for (int nt = 0; nt < 4; nt++) {
            int n = n0 + warp_n * 32 + nt * 8 + col_in;
            float b0 = bias[n], b1 = bias[n + 1];
            #pragma unroll
            for (int half = 0; half < 2; half++) {
                int m = m0 + warp_m * 64 + mt * 16 + row_in + half * 8;
                float2 o;
                o.x = acc[mt][nt][half * 2 + 0] + b0;
                o.y = acc[mt][nt][half * 2 + 1] + b1;
                *reinterpret_cast<float2*>(C + (size_t)m * N + n) = o;
            }
        }
    }
}

// ---------------------------------------------------------------------------
// A-resident K=256 v-projection with cp.async double-buffered B.
// Output head-major: v[h][HW][32] bf16 (each warp writes one head).
// ---------------------------------------------------------------------------
#define ASTRIDE 264   // 132 words; 132 % 8 == 4 -> conflict-free ldmatrix
#define K256 256
#define VB_BUF (128 * MSTR)                         // elems per B buffer
#define KSMEM_TOTAL (128 * ASTRIDE * 2 + 2 * VB_BUF * 2)

__global__ void __launch_bounds__(256, 2)
mma_k256_vproj(const float* __restrict__ A, const __nv_bfloat16* __restrict__ B,
               const float* __restrict__ bias, __nv_bfloat16* __restrict__ VT) {
    extern __shared__ __nv_bfloat16 sm[];
    __nv_bfloat16* As = sm;
    __nv_bfloat16* Bs = sm + 128 * ASTRIDE;
    const uint32_t as_base = smem_to_u32(As);
    const uint32_t bs_base = smem_to_u32(Bs);

    const int tid  = threadIdx.x;
    const int wid  = tid >> 5;
    const int lane = tid & 31;
    const int warp_m = wid >> 2;
    const int warp_n = wid & 3;
    const int m0 = blockIdx.x * 128;

    // ---- resident A slab 128x256 fp32 -> bf16 ----
    #pragma unroll
    for (int i = 0; i < 32; i++) {
        int e = i * 256 + tid;
        int r = e >> 6;
        int c = (e & 63) << 2;
        float4 av = *reinterpret_cast<const float4*>(A + (size_t)(m0 + r) * K256 + c);
        uint32_t p0, p1;
        asm("cvt.rn.satfinite.bf16x2.f32 %0, %1, %2;" : "=r"(p0) : "f"(av.y), "f"(av.x));
        asm("cvt.rn.satfinite.bf16x2.f32 %0, %1, %2;" : "=r"(p1) : "f"(av.w), "f"(av.z));
        uint32_t addr = as_base + (uint32_t)(r * ASTRIDE + c) * 2;
        asm volatile("st.shared.v2.b32 [%0], {%1, %2};" :: "r"(addr), "r"(p0), "r"(p1));
    }

    const int l16 = lane & 15;
    const uint32_t a_lm_off = (uint32_t)((warp_m * 64 + l16) * ASTRIDE + (lane >> 4) * 8) * 2;
    const uint32_t b_lm_off = (uint32_t)((warp_n * 32 + (l16 & 7)) * MSTR + ((l16 >> 3) * 8)) * 2;
    const int row_in = lane >> 2;
    const int col_in = (lane & 3) << 1;

    // cp.async B-tile loader lambda-style: 8KB per (nh, ks8) stage, 2 chunks/thread
    const int br = tid >> 2;            // row 0..63? No: e>>2 with e=i*256+tid
    for (int nh = 0; nh < 2; nh++) {
        const int n0 = nh * 128;
        float acc[4][4][4];
        #pragma unroll
        for (int i = 0; i < 4; i++)
            #pragma unroll
            for (int j = 0; j < 4; j++)
                #pragma unroll
                for (int r = 0; r < 4; r++) acc[i][j][r] = 0.f;

        // preload stage 0
        #pragma unroll
        for (int i = 0; i < 2; i++) {
            int e = i * 256 + tid;
            int r = e >> 2;
            int c = (e & 3) << 3;
            uint32_t dst = bs_base + (uint32_t)(r * MSTR + c) * 2;
            const __nv_bfloat16* src = B + (size_t)(n0 + r) * K256 + c;
            CP_ASYNC16(dst, src);
        }
        CP_COMMIT();
        CP_WAIT0();
        __syncthreads();   // also covers A-store visibility on nh==0

        for (int ks8 = 0; ks8 < 8; ks8++) {
            int cur = ks8 & 1;
            // prefetch next stage
            if (ks8 < 7) {
                uint32_t dbuf = bs_base + (uint32_t)((cur ^ 1) * VB_BUF) * 2;
                #pragma unroll
                for (int i = 0; i < 2; i++) {
                    int e = i * 256 + tid;
                    int r = e >> 2;
                    int c = (e & 3) << 3;
                    uint32_t dst = dbuf + (uint32_t)(r * MSTR + c) * 2;
                    const __nv_bfloat16* src = B + (size_t)(n0 + r) * K256 + (ks8 + 1) * 32 + c;
                    CP_ASYNC16(dst, src);
                }
                CP_COMMIT();
            }
            uint32_t cbuf = bs_base + (uint32_t)(cur * VB_BUF) * 2;
            #pragma unroll
            for (int sub = 0; sub < 2; sub++) {
                int kk = ks8 * 32 + sub * 16;
                uint32_t af[4][4];
                #pragma unroll
                for (int mt = 0; mt < 4; mt++) {
                    uint32_t addr = as_base + a_lm_off + (uint32_t)(mt * 16 * ASTRIDE + kk) * 2;
                    asm volatile("ldmatrix.sync.aligned.m8n8.x4.shared.b16 {%0,%1,%2,%3}, [%4];"
                        : "=r"(af[mt][0]), "=r"(af[mt][1]), "=r"(af[mt][2]), "=r"(af[mt][3])
                        : "r"(addr));
                }
                uint32_t bf[4][2];
                #pragma unroll
                for (int nt = 0; nt < 4; nt++) {
                    uint32_t addr = cbuf + b_lm_off + (uint32_t)(nt * 8 * MSTR + sub * 16) * 2;
                    asm volatile("ldmatrix.sync.aligned.m8n8.x2.shared.b16 {%0,%1}, [%2];"
                        : "=r"(bf[nt][0]), "=r"(bf[nt][1]) : "r"(addr));
                }
                #pragma unroll
                for (int mt = 0; mt < 4; mt++)
                    #pragma unroll
                    for (int nt = 0; nt < 4; nt++) {
                        asm volatile(
                            "mma.sync.aligned.m16n8k16.row.col.f32.bf16.bf16.f32 "
                            "{%0,%1,%2,%3}, {%4,%5,%6,%7}, {%8,%9}, {%0,%1,%2,%3};"
                            : "+f"(acc[mt][nt][0]), "+f"(acc[mt][nt][1]),
                              "+f"(acc[mt][nt][2]), "+f"(acc[mt][nt][3])
                            : "r"(af[mt][0]), "r"(af[mt][1]), "r"(af[mt][2]), "r"(af[mt][3]),
                              "r"(bf[nt][0]), "r"(bf[nt][1]));
                    }
            }
            if (ks8 < 7) { CP_WAIT0(); }
            __syncthreads();
        }

        // epilogue: each warp owns head (nh*4 + warp_n); layout v[h][HW][32]
        const int head = nh * 4 + warp_n;
        __nv_bfloat16* vh = VT + (size_t)head * HWSZ * HD;
        #pragma unroll
        for (int mt = 0; mt < 4; mt++) {
            #pragma unroll
            for (int nt = 0; nt < 4; nt++) {
                int ch = nt * 8 + col_in;
                int n = n0 + warp_n * 32 + ch;
                float b0 = bias[n], b1 = bias[n + 1];
                #pragma unroll
                for (int half = 0; half < 2; half++) {
                    int m = m0 + warp_m * 64 + mt * 16 + row_in + half * 8;
                    float ox = acc[mt][nt][half * 2 + 0] + b0;
                    float oy = acc[mt][nt][half * 2 + 1] + b1;
                    uint32_t pr;
                    asm("cvt.rn.satfinite.bf16x2.f32 %0, %1, %2;" : "=r"(pr) : "f"(oy), "f"(ox));
                    *reinterpret_cast<uint32_t*>(vh + (size_t)m * HD + ch) = pr;
                }
            }
        }
        __syncthreads();
    }
    (void)br;
}

// ---------------------------------------------------------------------------
// Fused weight prep: all fp32->bf16 conversions in one launch
// ---------------------------------------------------------------------------
__global__ void prep_all(const float* __restrict__ Wv,  __nv_bfloat16* __restrict__ dWv,
                         const float* __restrict__ Wo,  __nv_bfloat16* __restrict__ dWo,
                         const float* __restrict__ Wp2, __nv_bfloat16* __restrict__ dWp2,
                         const float* __restrict__ Wp3, __nv_bfloat16* __restrict__ dWp3,
                         const float* __restrict__ W1,  __nv_bfloat16* __restrict__ dW1,
                         const float* __restrict__ W2,  __nv_bfloat16* __restrict__ dW2) {
    int i = blockIdx.x * 256 + threadIdx.x;
    const int S = DIM * DIM;         // 65536
    const int L = DFF * DIM;         // 262144
    if (i < S)                    dWv[i] = __float2bfloat16(Wv[i]);
    else if (i < 2 * S)           dWo[i - S] = __float2bfloat16(Wo[i - S]);
    else if (i < 3 * S)           dWp2[i - 2 * S] = __float2bfloat16(Wp2[i - 2 * S]);
    else if (i < 4 * S)           dWp3[i - 3 * S] = __float2bfloat16(Wp3[i - 3 * S]);
    else if (i < 4 * S + L)       dW1[i - 4 * S] = __float2bfloat16(W1[i - 4 * S]);
    else if (i < 4 * S + 2 * L)   dW2[i - 4 * S - L] = __float2bfloat16(W2[i - 4 * S - L]);
}

__global__ void pack_wab(const float* __restrict__ Wa, const float* __restrict__ Wb,
                         const float* __restrict__ ba, const float* __restrict__ bb,
                         __nv_bfloat16* __restrict__ Whi, __nv_bfloat16* __restrict__ Wlo,
                         float* __restrict__ bab) {
    int row = blockIdx.x;
    int col = threadIdx.x;
    float w = 0.f;
    if (row < 200)      w = Wa[row * DIM + col];
    else if (row < 240) w = Wb[(row - 200) * DIM + col];
    __nv_bfloat16 hi = __float2bfloat16(w);
    Whi[row * DIM + col] = hi;
    Wlo[row * DIM + col] = __float2bfloat16(w - __bfloat162float(hi));
    if (col == 0) {
        float b = 0.f;
        if (row < 200)      b = ba[row];
        else if (row < 240) b = bb[row - 200];
        bab[row] = b;
    }
}

// ---------------------------------------------------------------------------
// fp32 SGEMM (tiny K=8 first pos-MLP layer)
// ---------------------------------------------------------------------------
#define BM 64
#define BN 64
#define BKT 16

__global__ void sgemm_k8_relu(const float* __restrict__ A, const float* __restrict__ B,
                              const float* __restrict__ bias, float* __restrict__ C,
                              int M, int N, int K) {
    __shared__ float As[BKT][BM];
    __shared__ float Bs[BKT][BN];
    const int tid  = threadIdx.x;
    const int brow = blockIdx.y * BM;
    const int bcol = blockIdx.x * BN;
    const int tx = tid & 15;
    const int ty = tid >> 4;
    const int lr = tid >> 2;
    const int lk = (tid & 3) << 2;

    float acc[4][4] = {};
    for (int k0 = 0; k0 < K; k0 += BKT) {
        #pragma unroll
        for (int i = 0; i < 4; i++) {
            int k = k0 + lk + i;
            As[lk + i][lr] = (k < K) ? A[(size_t)(brow + lr) * K + k] : 0.f;
            Bs[lk + i][lr] = (k < K) ? B[(size_t)(bcol + lr) * K + k] : 0.f;
        }
        __syncthreads();
        #pragma unroll
        for (int kk = 0; kk < BKT; kk++) {
            float4 a4 = *reinterpret_cast<const float4*>(&As[kk][ty << 2]);
            float4 b4 = *reinterpret_cast<const float4*>(&Bs[kk][tx << 2]);
            float ar[4] = {a4.x, a4.y, a4.z, a4.w};
            float br[4] = {b4.x, b4.y, b4.z, b4.w};
            #pragma unroll
            for (int i = 0; i < 4; i++)
                #pragma unroll
                for (int j = 0; j < 4; j++)
                    acc[i][j] = fmaf(ar[i], br[j], acc[i][j]);
        }
        __syncthreads();
    }
    #pragma unroll
    for (int i = 0; i < 4; i++) {
        int r = brow + (ty << 2) + i;
        #pragma unroll
        for (int j = 0; j < 4; j++) {
            int c = bcol + (tx << 2) + j;
            C[(size_t)r * N + c] = fmaxf(acc[i][j] + bias[c], 0.f);
        }
    }
}

// ---------------------------------------------------------------------------
// Deformable bilinear sampling, fused softmax; v head-major [h][HW][32] bf16.
// Corner pairs (x, x+1) are adjacent 64B blocks -> L1-line locality.
// ---------------------------------------------------------------------------
__global__ void sample_kernel(const float* __restrict__ rw,
                              const float* __restrict__ ao,
                              const __nv_bfloat16* __restrict__ v,
                              float* __restrict__ out) {
    int n    = blockIdx.x;
    int h    = threadIdx.x >> 5;
    int lane = threadIdx.x & 31;

    const float* aon = ao + (size_t)n * DIM;
    float logit = (lane < PP) ? aon[h * PP + lane] : -1e30f;
    float mx = logit;
    #pragma unroll
    for (int o = 16; o; o >>= 1) mx = fmaxf(mx, __shfl_xor_sync(0xffffffffu, mx, o));
    float e = (lane < PP) ? expf(logit - mx) : 0.f;
    float s = e;
    #pragma unroll
    for (int o = 16; o; o >>= 1) s += __shfl_xor_sync(0xffffffffu, s, o);
    float myattn = e / s;

    const float* rwn = rw + (size_t)n * 8;
    float rw0 = rwn[0], rw1 = rwn[1], rw3 = rwn[3], rw4 = rwn[4], rw6 = rwn[6];
    const float* offn = aon + 200 + h * 5;
    float o0 = offn[0], o1 = offn[1], o2 = offn[2], o3 = offn[3], o4 = offn[4];

    float cx = rw0 + o0 * 0.125f * rw3;
    float cy = rw1 + o1 * 0.125f * rw4;
    float sx = fmaxf(rw3 + o2 * 0.125f * rw3, 0.f);
    float sy = fmaxf(rw4 + o3 * 0.125f * rw4, 0.f);
    float ang = (rw6 + o4 * (1.0f / 16.0f)) * 6.2831853071795864769f;
    float sth, cth;
    sincosf(ang, &sth, &cth);

    const __nv_bfloat16* vh = v + (size_t)h * HWSZ * HD + lane;

    float acc = 0.f;
    #pragma unroll
    for (int p = 0; p < PP; p++) {
        int a = p / 5, b = p % 5;
        float gx = sx * (float)(b - 2) * 0.2f;
        float gy = sy * (float)(a - 2) * 0.2f;
        float lx = cx + gx * cth - gy * sth;
        float ly = cy + gx * sth + gy * cth;
        float x = lx * (float)WW - 0.5f;
        float y = ly * (float)HH - 0.5f;
        float x0f = floorf(x), y0f = floorf(y);
        float fx = x - x0f, fy = y - y0f;
        int x0 = (int)x0f, y0 = (int)y0f;
        float ap = __shfl_sync(0xffffffffu, myattn, p);
        #pragma unroll
        for (int c = 0; c < 4; c++) {
            int dx = c & 1, dy = c >> 1;
            int xi = x0 + dx, yi = y0 + dy;
            float wx = dx ? fx : (1.f - fx);
            float wy = dy ? fy : (1.f - fy);
            bool valid = (xi >= 0) && (xi <= WW - 1) && (yi >= 0) && (yi <= HH - 1);
            if (valid) {
                float g = __bfloat162float(vh[(size_t)(yi * WW + xi) * HD]);
                acc = fmaf(ap * wx * wy, g, acc);
            }
        }
    }
    out[(size_t)n * DIM + h * HD + lane] = acc;
}

// ---------------------------------------------------------------------------
// LayerNorm (residual add + LN)
// ---------------------------------------------------------------------------
__global__ void ln_kernel(const float* __restrict__ A, const float* __restrict__ Bb,
                          const float* __restrict__ gamma, const float* __restrict__ beta,
                          float* __restrict__ O) {
    int n = blockIdx.x;
    int c = threadIdx.x;
    float x = A[(size_t)n * DIM + c] + Bb[(size_t)n * DIM + c];
    float s = x, sq = x * x;
    #pragma unroll
    for (int o = 16; o; o >>= 1) {
        s  += __shfl_xor_sync(0xffffffffu, s, o);
        sq += __shfl_xor_sync(0xffffffffu, sq, o);
    }
    __shared__ float sh_s[8], sh_q[8];
    if ((c & 31) == 0) { sh_s[c >> 5] = s; sh_q[c >> 5] = sq; }
    __syncthreads();
    float ts = 0.f, tq = 0.f;
    #pragma unroll
    for (int i = 0; i < 8; i++) { ts += sh_s[i]; tq += sh_q[i]; }
    float mean = ts * (1.0f / (float)DIM);
    float var  = tq * (1.0f / (float)DIM) - mean * mean;
    var = fmaxf(var, 0.f);
    float inv = rsqrtf(var + 1e-5f);
    O[(size_t)n * DIM + c] = (x - mean) * inv * gamma[c] + beta[c];
}

// ---------------------------------------------------------------------------
// Host orchestration
// ---------------------------------------------------------------------------
extern "C" void kernel_launch(void* const* d_in, const int* in_sizes, int n_in,
                              void* d_out, int out_size) {
    const float* query = (const float*)d_in[0];
    const float* memory = (const float*)d_in[1];
    const float* ref_w  = (const float*)d_in[2];
    const float* Wp1 = (const float*)d_in[5];
    const float* bp1 = (const float*)d_in[6];
    const float* Wp2 = (const float*)d_in[7];
    const float* bp2 = (const float*)d_in[8];
    const float* Wp3 = (const float*)d_in[9];
    const float* bp3 = (const float*)d_in[10];
    const float* Wv  = (const float*)d_in[11];
    const float* bv  = (const float*)d_in[12];
    const float* Wa  = (const float*)d_in[13];
    const float* ba  = (const float*)d_in[14];
    const float* Wb  = (const float*)d_in[15];
    const float* bb  = (const float*)d_in[16];
    const float* Wo  = (const float*)d_in[17];
    const float* bo  = (const float*)d_in[18];
    const float* W1  = (const float*)d_in[19];
    const float* b1  = (const float*)d_in[20];
    const float* W2  = (const float*)d_in[21];
    const float* b2  = (const float*)d_in[22];
    const float* g2  = (const float*)d_in[23];
    const float* be2 = (const float*)d_in[24];
    const float* g3  = (const float*)d_in[25];
    const float* be3 = (const float*)d_in[26];
    float* out = (float*)d_out;

    __nv_bfloat16 *v_bf, *Wv_bf, *Wo_bf, *W1_bf, *W2_bf, *Wp2_bf, *Wp3_bf, *Wab_hi, *Wab_lo;
    float *q, *buf1, *buf2, *smp, *xq, *bab;
    cudaGetSymbolAddress((void**)&v_bf,   g_v_bf);
    cudaGetSymbolAddress((void**)&q,      g_q);
    cudaGetSymbolAddress((void**)&buf1,   g_buf1);
    cudaGetSymbolAddress((void**)&buf2,   g_buf2);
    cudaGetSymbolAddress((void**)&smp,    g_smp);
    cudaGetSymbolAddress((void**)&xq,     g_xq);
    cudaGetSymbolAddress((void**)&Wv_bf,  g_Wv_bf);
    cudaGetSymbolAddress((void**)&Wo_bf,  g_Wo_bf);
    cudaGetSymbolAddress((void**)&W1_bf,  g_W1_bf);
    cudaGetSymbolAddress((void**)&W2_bf,  g_W2_bf);
    cudaGetSymbolAddress((void**)&Wp2_bf, g_Wp2_bf);
    cudaGetSymbolAddress((void**)&Wp3_bf, g_Wp3_bf);
    cudaGetSymbolAddress((void**)&Wab_hi, g_Wab_hi);
    cudaGetSymbolAddress((void**)&Wab_lo, g_Wab_lo);
    cudaGetSymbolAddress((void**)&bab,    g_bab);

    cudaFuncSetAttribute(mma_k256_vproj, cudaFuncAttributeMaxDynamicSharedMemorySize, KSMEM_TOTAL);

    // 0) Weight prep (single fused launch + pack)
    const int PREP_N = 4 * DIM * DIM + 2 * DFF * DIM;
    prep_all<<<(PREP_N + 255) / 256, 256>>>(Wv, Wv_bf, Wo, Wo_bf, Wp2, Wp2_bf,
                                            Wp3, Wp3_bf, W1, W1_bf, W2, W2_bf);
    pack_wab<<<DIM, DIM>>>(Wa, Wb, ba, bb, Wab_hi, Wab_lo, bab);

    // 1) Positional MLP
    sgemm_k8_relu<<<dim3(DIM / BN, NQ / BM), 256>>>(ref_w, Wp1, bp1, buf1, NQ, DIM, 8);
    mma_gemm<1><<<dim3(2, NQ / MBM), 256>>>(buf1, Wp2_bf, bp2, nullptr, buf2, DIM, DIM);
    mma_gemm<2><<<dim3(2, NQ / MBM), 256>>>(buf2, Wp3_bf, bp3, query, q, DIM, DIM);

    // 2) Value projection -> head-major bf16 v
    mma_k256_vproj<<<HWSZ / 128, 256, KSMEM_TOTAL>>>(memory, Wv_bf, bv, v_bf);

    // 3) Attn-logits + offsets (bf16x3, near-fp32)
    mma_gemm_x3<<<dim3(2, NQ / MBM), 256>>>(q, Wab_hi, Wab_lo, bab, buf1, DIM, DIM);

    // 4) Sampling (fused softmax)
    sample_kernel<<<NQ, 256>>>(ref_w, buf1, v_bf, smp);

    // 5) Output projection + residual LN
    mma_gemm<0><<<dim3(2, NQ / MBM), 256>>>(smp, Wo_bf, bo, nullptr, buf2, DIM, DIM);
    ln_kernel<<<NQ, 256>>>(query, buf2, g2, be2, xq);

    // 6) FFN + final LN
    mma_gemm<1><<<dim3(DFF / MBN, NQ / MBM), 256>>>(xq, W1_bf, b1, nullptr, buf1, DIM, DFF);
    mma_gemm<0><<<dim3(2, NQ / MBM), 256>>>(buf1, W2_bf, b2, nullptr, buf2, DFF, DIM);
    ln_kernel<<<NQ, 256>>>(xq, buf2, g3, be3, out);
}

// round 7
// speedup vs baseline: 4.3904x; 1.0237x over previous
#include <cuda_runtime.h>
#include <cuda_bf16.h>
#include <math.h>
#include <cstdint>

// Problem constants
#define NQ   8192
#define DIM  256
#define NH   8
#define HD   32
#define PP   25
#define HH   512
#define WW   512
#define HWSZ (HH * WW)
#define DFF  1024

// ---------------------------------------------------------------------------
// Scratch (device globals)
// ---------------------------------------------------------------------------
__device__ __nv_bfloat16 g_v_bf[(size_t)NH * HWSZ * HD];  // head-major value tensor
__device__ float g_q[NQ * DIM];
__device__ float g_buf1[NQ * DFF];
__device__ float g_buf2[NQ * DIM];
__device__ float g_smp[NQ * DIM];
__device__ float g_xq[NQ * DIM];
__device__ __nv_bfloat16 g_Wv_bf[DIM * DIM];
__device__ __nv_bfloat16 g_Wo_bf[DIM * DIM];
__device__ __nv_bfloat16 g_W1_bf[DFF * DIM];
__device__ __nv_bfloat16 g_W2_bf[DIM * DFF];
__device__ __nv_bfloat16 g_Wp2_bf[DIM * DIM];
__device__ __nv_bfloat16 g_Wp3_bf[DIM * DIM];
__device__ __nv_bfloat16 g_Wab_hi[DIM * DIM];
__device__ __nv_bfloat16 g_Wab_lo[DIM * DIM];
__device__ float g_bab[DIM];

__device__ __forceinline__ uint32_t smem_to_u32(const void* p) {
    uint32_t a;
    asm("{ .reg .u64 t; cvta.to.shared.u64 t, %1; cvt.u32.u64 %0, t; }" : "=r"(a) : "l"(p));
    return a;
}
#define CP_ASYNC16(dst, src) \
    asm volatile("cp.async.cg.shared.global [%0], [%1], 16;" :: "r"(dst), "l"(src))
#define CP_COMMIT() asm volatile("cp.async.commit_group;" ::: "memory")
#define CP_WAIT0()  asm volatile("cp.async.wait_group 0;" ::: "memory")

#define MBM 128
#define MBN 128
#define MBK 32
#define MSTR 40   // smem row stride: 20 words, 20 % 8 == 4 -> conflict-free ldmatrix

// ---------------------------------------------------------------------------
// 128x128 warp-MMA bf16 GEMM (used for FFN1, large-grid cases)
// EPI: 0=+bias, 1=+bias+relu, 2=+bias+Res
// ---------------------------------------------------------------------------
template <int EPI>
__global__ void __launch_bounds__(256, 2)
mma_gemm(const float* __restrict__ A, const __nv_bfloat16* __restrict__ B,
         const float* __restrict__ bias, const float* __restrict__ Res,
         float* __restrict__ C, int K, int N) {
    __shared__ __nv_bfloat16 As[MBM * MSTR];
    __shared__ __nv_bfloat16 Bs[MBN * MSTR];
    const uint32_t as_base = smem_to_u32(As);
    const uint32_t bs_base = smem_to_u32(Bs);

    const int tid  = threadIdx.x;
    const int wid  = tid >> 5;
    const int lane = tid & 31;
    const int warp_m = wid >> 2;
    const int warp_n = wid & 3;
    const int m0 = blockIdx.y * MBM;
    const int n0 = blockIdx.x * MBN;

    float acc[4][4][4];
    #pragma unroll
    for (int i = 0; i < 4; i++)
        #pragma unroll
        for (int j = 0; j < 4; j++)
            #pragma unroll
            for (int r = 0; r < 4; r++) acc[i][j][r] = 0.f;

    const int l16 = lane & 15;
    const uint32_t a_lm_off = (uint32_t)((warp_m * 64 + l16) * MSTR + (lane >> 4) * 8) * 2;
    const uint32_t b_lm_off = (uint32_t)((warp_n * 32 + (l16 & 7)) * MSTR + ((l16 >> 3) * 8)) * 2;

    for (int k0 = 0; k0 < K; k0 += MBK) {
        #pragma unroll
        for (int i = 0; i < 4; i++) {
            int e = i * 256 + tid;
            int r = e >> 3;
            int c = (e & 7) << 2;
            float4 av = *reinterpret_cast<const float4*>(A + (size_t)(m0 + r) * K + k0 + c);
            uint32_t p0, p1;
            asm("cvt.rn.satfinite.bf16x2.f32 %0, %1, %2;" : "=r"(p0) : "f"(av.y), "f"(av.x));
            asm("cvt.rn.satfinite.bf16x2.f32 %0, %1, %2;" : "=r"(p1) : "f"(av.w), "f"(av.z));
            uint32_t addr = as_base + (uint32_t)(r * MSTR + c) * 2;
            asm volatile("st.shared.v2.b32 [%0], {%1, %2};" :: "r"(addr), "r"(p0), "r"(p1));
        }
        #pragma unroll
        for (int i = 0; i < 2; i++) {
            int e = i * 256 + tid;
            int r = e >> 2;
            int c = (e & 3) << 3;
            uint4 bv = *reinterpret_cast<const uint4*>(B + (size_t)(n0 + r) * K + k0 + c);
            uint32_t addr = bs_base + (uint32_t)(r * MSTR + c) * 2;
            asm volatile("st.shared.v4.b32 [%0], {%1, %2, %3, %4};"
                :: "r"(addr), "r"(bv.x), "r"(bv.y), "r"(bv.z), "r"(bv.w));
        }
        __syncthreads();

        #pragma unroll
        for (int ks = 0; ks < 2; ks++) {
            uint32_t af[4][4];
            #pragma unroll
            for (int mt = 0; mt < 4; mt++) {
                uint32_t addr = as_base + a_lm_off + (uint32_t)(mt * 16 * MSTR + ks * 16) * 2;
                asm volatile("ldmatrix.sync.aligned.m8n8.x4.shared.b16 {%0,%1,%2,%3}, [%4];"
                    : "=r"(af[mt][0]), "=r"(af[mt][1]), "=r"(af[mt][2]), "=r"(af[mt][3])
                    : "r"(addr));
            }
            uint32_t bf[4][2];
            #pragma unroll
            for (int nt = 0; nt < 4; nt++) {
                uint32_t addr = bs_base + b_lm_off + (uint32_t)(nt * 8 * MSTR + ks * 16) * 2;
                asm volatile("ldmatrix.sync.aligned.m8n8.x2.shared.b16 {%0,%1}, [%2];"
                    : "=r"(bf[nt][0]), "=r"(bf[nt][1]) : "r"(addr));
            }
            #pragma unroll
            for (int mt = 0; mt < 4; mt++)
                #pragma unroll
                for (int nt = 0; nt < 4; nt++) {
                    asm volatile(
                        "mma.sync.aligned.m16n8k16.row.col.f32.bf16.bf16.f32 "
                        "{%0,%1,%2,%3}, {%4,%5,%6,%7}, {%8,%9}, {%0,%1,%2,%3};"
                        : "+f"(acc[mt][nt][0]), "+f"(acc[mt][nt][1]),
                          "+f"(acc[mt][nt][2]), "+f"(acc[mt][nt][3])
                        : "r"(af[mt][0]), "r"(af[mt][1]), "r"(af[mt][2]), "r"(af[mt][3]),
                          "r"(bf[nt][0]), "r"(bf[nt][1]));
                }
        }
        __syncthreads();
    }

    const int row_in = lane >> 2;
    const int col_in = (lane & 3) << 1;
    #pragma unroll
    for (int mt = 0; mt < 4; mt++) {
        #pragma unroll
        for (int nt = 0; nt < 4; nt++) {
            int n = n0 + warp_n * 32 + nt * 8 + col_in;
            float b0 = bias[n], b1 = bias[n + 1];
            #pragma unroll
            for (int half = 0; half < 2; half++) {
                int m = m0 + warp_m * 64 + mt * 16 + row_in + half * 8;
                float2 o;
                o.x = acc[mt][nt][half * 2 + 0] + b0;
                o.y = acc[mt][nt][half * 2 + 1] + b1;
                if (EPI == 1) { o.x = fmaxf(o.x, 0.f); o.y = fmaxf(o.y, 0.f); }
                if (EPI == 2) {
                    float2 rr = *reinterpret_cast<const float2*>(Res + (size_t)m * N + n);
                    o.x += rr.x; o.y += rr.y;
                }
                *reinterpret_cast<float2*>(C + (size_t)m * N + n) = o;
            }
        }
    }
}

// ---------------------------------------------------------------------------
// 64x128-tile warp-MMA bf16 GEMM — high-occupancy variant for M=8192/N=256
// 8 warps: warp grid 2x4, each warp 32x32 (2x4 m16n8k16). EPI as above.
// ---------------------------------------------------------------------------
template <int EPI>
__global__ void __launch_bounds__(256, 3)
mma_gemm64(const float* __restrict__ A, const __nv_bfloat16* __restrict__ B,
           const float* __restrict__ bias, const float* __restrict__ Res,
           float* __restrict__ C, int K, int N) {
    __shared__ __nv_bfloat16 As[64 * MSTR];
    __shared__ __nv_bfloat16 Bs[MBN * MSTR];
    const uint32_t as_base = smem_to_u32(As);
    const uint32_t bs_base = smem_to_u32(Bs);

    const int tid  = threadIdx.x;
    const int wid  = tid >> 5;
    const int lane = tid & 31;
    const int warp_m = wid >> 2;        // 0..1 (32 rows each)
    const int warp_n = wid & 3;         // 0..3 (32 cols each)
    const int m0 = blockIdx.y * 64;
    const int n0 = blockIdx.x * MBN;

    float acc[2][4][4];
    #pragma unroll
    for (int i = 0; i < 2; i++)
        #pragma unroll
        for (int j = 0; j < 4; j++)
            #pragma unroll
            for (int r = 0; r < 4; r++) acc[i][j][r] = 0.f;

    const int l16 = lane & 15;
    const uint32_t a_lm_off = (uint32_t)((warp_m * 32 + l16) * MSTR + (lane >> 4) * 8) * 2;
    const uint32_t b_lm_off = (uint32_t)((warp_n * 32 + (l16 & 7)) * MSTR + ((l16 >> 3) * 8)) * 2;

    for (int k0 = 0; k0 < K; k0 += MBK) {
        #pragma unroll
        for (int i = 0; i < 2; i++) {
            int e = i * 256 + tid;
            int r = e >> 3;
            int c = (e & 7) << 2;
            float4 av = *reinterpret_cast<const float4*>(A + (size_t)(m0 + r) * K + k0 + c);
            uint32_t p0, p1;
            asm("cvt.rn.satfinite.bf16x2.f32 %0, %1, %2;" : "=r"(p0) : "f"(av.y), "f"(av.x));
            asm("cvt.rn.satfinite.bf16x2.f32 %0, %1, %2;" : "=r"(p1) : "f"(av.w), "f"(av.z));
            uint32_t addr = as_base + (uint32_t)(r * MSTR + c) * 2;
            asm volatile("st.shared.v2.b32 [%0], {%1, %2};" :: "r"(addr), "r"(p0), "r"(p1));
        }
        #pragma unroll
        for (int i = 0; i < 2; i++) {
            int e = i * 256 + tid;
            int r = e >> 2;
            int c = (e & 3) << 3;
            uint4 bv = *reinterpret_cast<const uint4*>(B + (size_t)(n0 + r) * K + k0 + c);
            uint32_t addr = bs_base + (uint32_t)(r * MSTR + c) * 2;
            asm volatile("st.shared.v4.b32 [%0], {%1, %2, %3, %4};"
                :: "r"(addr), "r"(bv.x), "r"(bv.y), "r"(bv.z), "r"(bv.w));
        }
        __syncthreads();

        #pragma unroll
        for (int ks = 0; ks < 2; ks++) {
            uint32_t af[2][4];
            #pragma unroll
            for (int mt = 0; mt < 2; mt++) {
                uint32_t addr = as_base + a_lm_off + (uint32_t)(mt * 16 * MSTR + ks * 16) * 2;
                asm volatile("ldmatrix.sync.aligned.m8n8.x4.shared.b16 {%0,%1,%2,%3}, [%4];"
                    : "=r"(af[mt][0]), "=r"(af[mt][1]), "=r"(af[mt][2]), "=r"(af[mt][3])
                    : "r"(addr));
            }
            uint32_t bf[4][2];
            #pragma unroll
            for (int nt = 0; nt < 4; nt++) {
                uint32_t addr = bs_base + b_lm_off + (uint32_t)(nt * 8 * MSTR + ks * 16) * 2;
                asm volatile("ldmatrix.sync.aligned.m8n8.x2.shared.b16 {%0,%1}, [%2];"
                    : "=r"(bf[nt][0]), "=r"(bf[nt][1]) : "r"(addr));
            }
            #pragma unroll
            for (int mt = 0; mt < 2; mt++)
                #pragma unroll
                for (int nt = 0; nt < 4; nt++) {
                    asm volatile(
                        "mma.sync.aligned.m16n8k16.row.col.f32.bf16.bf16.f32 "
                        "{%0,%1,%2,%3}, {%4,%5,%6,%7}, {%8,%9}, {%0,%1,%2,%3};"
                        : "+f"(acc[mt][nt][0]), "+f"(acc[mt][nt][1]),
                          "+f"(acc[mt][nt][2]), "+f"(acc[mt][nt][3])
                        : "r"(af[mt][0]), "r"(af[mt][1]), "r"(af[mt][2]), "r"(af[mt][3]),
                          "r"(bf[nt][0]), "r"(bf[nt][1]));
                }
        }
        __syncthreads();
    }

    const int row_in = lane >> 2;
    const int col_in = (lane & 3) << 1;
    #pragma unroll
    for (int mt = 0; mt < 2; mt++) {
        #pragma unroll
        for (int nt = 0; nt < 4; nt++) {
            int n = n0 + warp_n * 32 + nt * 8 + col_in;
            float b0 = bias[n], b1 = bias[n + 1];
            #pragma unroll
            for (int half = 0; half < 2; half++) {
                int m = m0 + warp_m * 32 + mt * 16 + row_in + half * 8;
                float2 o;
                o.x = acc[mt][nt][half * 2 + 0] + b0;
                o.y = acc[mt][nt][half * 2 + 1] + b1;
                if (EPI == 1) { o.x = fmaxf(o.x, 0.f); o.y = fmaxf(o.y, 0.f); }
                if (EPI == 2) {
                    float2 rr = *reinterpret_cast<const float2*>(Res + (size_t)m * N + n);
                    o.x += rr.x; o.y += rr.y;
                }
                *reinterpret_cast<float2*>(C + (size_t)m * N + n) = o;
            }
        }
    }
}

// ---------------------------------------------------------------------------
// bf16x3 split-precision MMA GEMM (near-fp32): attn-logits + offsets GEMM
// ---------------------------------------------------------------------------
__global__ void __launch_bounds__(256, 2)
mma_gemm_x3(const float* __restrict__ A, const __nv_bfloat16* __restrict__ Bhi,
            const __nv_bfloat16* __restrict__ Blo, const float* __restrict__ bias,
            float* __restrict__ C, int K, int N) {
    __shared__ __nv_bfloat16 AsH[MBM * MSTR];
    __shared__ __nv_bfloat16 AsL[MBM * MSTR];
    __shared__ __nv_bfloat16 BsH[MBN * MSTR];
    __shared__ __nv_bfloat16 BsL[MBN * MSTR];
    const uint32_t ash = smem_to_u32(AsH);
    const uint32_t asl = smem_to_u32(AsL);
    const uint32_t bsh = smem_to_u32(BsH);
    const uint32_t bsl = smem_to_u32(BsL);

    const int tid  = threadIdx.x;
    const int wid  = tid >> 5;
    const int lane = tid & 31;
    const int warp_m = wid >> 2;
    const int warp_n = wid & 3;
    const int m0 = blockIdx.y * MBM;
    const int n0 = blockIdx.x * MBN;

    float acc[4][4][4];
    #pragma unroll
    for (int i = 0; i < 4; i++)
        #pragma unroll
        for (int j = 0; j < 4; j++)
            #pragma unroll
            for (int r = 0; r < 4; r++) acc[i][j][r] = 0.f;

    const int l16 = lane & 15;
    const uint32_t a_lm_off = (uint32_t)((warp_m * 64 + l16) * MSTR + (lane >> 4) * 8) * 2;
    const uint32_t b_lm_off = (uint32_t)((warp_n * 32 + (l16 & 7)) * MSTR + ((l16 >> 3) * 8)) * 2;

    for (int k0 = 0; k0 < K; k0 += MBK) {
        #pragma unroll
        for (int i = 0; i < 4; i++) {
            int e = i * 256 + tid;
            int r = e >> 3;
            int c = (e & 7) << 2;
            float4 av = *reinterpret_cast<const float4*>(A + (size_t)(m0 + r) * K + k0 + c);
            __nv_bfloat16 hx = __float2bfloat16(av.x);
            __nv_bfloat16 hy = __float2bfloat16(av.y);
            __nv_bfloat16 hz = __float2bfloat16(av.z);
            __nv_bfloat16 hw = __float2bfloat16(av.w);
            __nv_bfloat162 h01; h01.x = hx; h01.y = hy;
            __nv_bfloat162 h23; h23.x = hz; h23.y = hw;
            uint32_t hp0 = *reinterpret_cast<uint32_t*>(&h01);
            uint32_t hp1 = *reinterpret_cast<uint32_t*>(&h23);
            float lx = av.x - __bfloat162float(hx);
            float ly = av.y - __bfloat162float(hy);
            float lz = av.z - __bfloat162float(hz);
            float lw = av.w - __bfloat162float(hw);
            uint32_t lp0, lp1;
            asm("cvt.rn.satfinite.bf16x2.f32 %0, %1, %2;" : "=r"(lp0) : "f"(ly), "f"(lx));
            asm("cvt.rn.satfinite.bf16x2.f32 %0, %1, %2;" : "=r"(lp1) : "f"(lw), "f"(lz));
            uint32_t off = (uint32_t)(r * MSTR + c) * 2;
            asm volatile("st.shared.v2.b32 [%0], {%1, %2};" :: "r"(ash + off), "r"(hp0), "r"(hp1));
            asm volatile("st.shared.v2.b32 [%0], {%1, %2};" :: "r"(asl + off), "r"(lp0), "r"(lp1));
        }
        #pragma unroll
        for (int i = 0; i < 2; i++) {
            int e = i * 256 + tid;
            int r = e >> 2;
            int c = (e & 3) << 3;
            uint4 bh = *reinterpret_cast<const uint4*>(Bhi + (size_t)(n0 + r) * K + k0 + c);
            uint4 bl = *reinterpret_cast<const uint4*>(Blo + (size_t)(n0 + r) * K + k0 + c);
            uint32_t off = (uint32_t)(r * MSTR + c) * 2;
            asm volatile("st.shared.v4.b32 [%0], {%1, %2, %3, %4};"
                :: "r"(bsh + off), "r"(bh.x), "r"(bh.y), "r"(bh.z), "r"(bh.w));
            asm volatile("st.shared.v4.b32 [%0], {%1, %2, %3, %4};"
                :: "r"(bsl + off), "r"(bl.x), "r"(bl.y), "r"(bl.z), "r"(bl.w));
        }
        __syncthreads();

        #pragma unroll
        for (int pass = 0; pass < 3; pass++) {
            uint32_t abase = (pass == 2) ? asl : ash;
            uint32_t bbase = (pass == 1) ? bsl : bsh;
            #pragma unroll
            for (int ks = 0; ks < 2; ks++) {
                uint32_t af[4][4];
                #pragma unroll
                for (int mt = 0; mt < 4; mt++) {
                    uint32_t addr = abase + a_lm_off + (uint32_t)(mt * 16 * MSTR + ks * 16) * 2;
                    asm volatile("ldmatrix.sync.aligned.m8n8.x4.shared.b16 {%0,%1,%2,%3}, [%4];"
                        : "=r"(af[mt][0]), "=r"(af[mt][1]), "=r"(af[mt][2]), "=r"(af[mt][3])
                        : "r"(addr));
                }
                uint32_t bf[4][2];
                #pragma unroll
                for (int nt = 0; nt < 4; nt++) {
                    uint32_t addr = bbase + b_lm_off + (uint32_t)(nt * 8 * MSTR + ks * 16) * 2;
                    asm volatile("ldmatrix.sync.aligned.m8n8.x2.shared.b16 {%0,%1}, [%2];"
                        : "=r"(bf[nt][0]), "=r"(bf[nt][1]) : "r"(addr));
                }
                #pragma unroll
                for (int mt = 0; mt < 4; mt++)
                    #pragma unroll
                    for (int nt = 0; nt < 4; nt++) {
                        asm volatile(
                            "mma.sync.aligned.m16n8k16.row.col.f32.bf16.bf16.f32 "
                            "{%0,%1,%2,%3}, {%4,%5,%6,%7}, {%8,%9}, {%0,%1,%2,%3};"
                            : "+f"(acc[mt][nt][0]), "+f"(acc[mt][nt][1]),
                              "+f"(acc[mt][nt][2]), "+f"(acc[mt][nt][3])
                            : "r"(af[mt][0]), "r"(af[mt][1]), "r"(af[mt][2]), "r"(af[mt][3]),
                              "r"(bf[nt][0]), "r"(bf[nt][1]));
                    }
            }
        }
        __syncthreads();
    }

    const int row_in = lane >> 2;
    const int col_in = (lane & 3) << 1;
    #pragma unroll
    for (int mt = 0; mt < 4; mt++) {
        #pragma unroll
        for (int nt = 0; nt < 4; nt++) {
            int n = n0 + warp_n * 32 + nt * 8 + col_in;
            float b0 = bias[n], b1 = bias[n + 1];
            #pragma unroll
            for (int half = 0; half < 2; half++) {
                int m = m0 + warp_m * 64 + mt * 16 + row_in + half * 8;
                float2 o;
                o.x = acc[mt][nt][half * 2 + 0] + b0;
                o.y = acc[mt][nt][half * 2 + 1] + b1;
                *reinterpret_cast<float2*>(C + (size_t)m * N + n) = o;
            }
        }
    }
}

// ---------------------------------------------------------------------------
// A-resident K=256 v-projection with cp.async double-buffered B.
// Output head-major: v[h][HW][32] bf16.
// ---------------------------------------------------------------------------
#define ASTRIDE 264
#define K256 256
#define VB_BUF (128 * MSTR)
#define KSMEM_TOTAL (128 * ASTRIDE * 2 + 2 * VB_BUF * 2)

__global__ void __launch_bounds__(256, 2)
mma_k256_vproj(const float* __restrict__ A, const __nv_bfloat16* __restrict__ B,
               const float* __restrict__ bias, __nv_bfloat16* __restrict__ VT) {
    extern __shared__ __nv_bfloat16 sm[];
    __nv_bfloat16* As = sm;
    __nv_bfloat16* Bs = sm + 128 * ASTRIDE;
    const uint32_t as_base = smem_to_u32(As);
    const uint32_t bs_base = smem_to_u32(Bs);

    const int tid  = threadIdx.x;
    const int wid  = tid >> 5;
    const int lane = tid & 31;
    const int warp_m = wid >> 2;
    const int warp_n = wid & 3;
    const int m0 = blockIdx.x * 128;

    #pragma unroll
    for (int i = 0; i < 32; i++) {
        int e = i * 256 + tid;
        int r = e >> 6;
        int c = (e & 63) << 2;
        float4 av = *reinterpret_cast<const float4*>(A + (size_t)(m0 + r) * K256 + c);
        uint32_t p0, p1;
        asm("cvt.rn.satfinite.bf16x2.f32 %0, %1, %2;" : "=r"(p0) : "f"(av.y), "f"(av.x));
        asm("cvt.rn.satfinite.bf16x2.f32 %0, %1, %2;" : "=r"(p1) : "f"(av.w), "f"(av.z));
        uint32_t addr = as_base + (uint32_t)(r * ASTRIDE + c) * 2;
        asm volatile("st.shared.v2.b32 [%0], {%1, %2};" :: "r"(addr), "r"(p0), "r"(p1));
    }

    const int l16 = lane & 15;
    const uint32_t a_lm_off = (uint32_t)((warp_m * 64 + l16) * ASTRIDE + (lane >> 4) * 8) * 2;
    const uint32_t b_lm_off = (uint32_t)((warp_n * 32 + (l16 & 7)) * MSTR + ((l16 >> 3) * 8)) * 2;
    const int row_in = lane >> 2;
    const int col_in = (lane & 3) << 1;

    for (int nh = 0; nh < 2; nh++) {
        const int n0 = nh * 128;
        float acc[4][4][4];
        #pragma unroll
        for (int i = 0; i < 4; i++)
            #pragma unroll
            for (int j = 0; j < 4; j++)
                #pragma unroll
                for (int r = 0; r < 4; r++) acc[i][j][r] = 0.f;

        #pragma unroll
        for (int i = 0; i < 2; i++) {
            int e = i * 256 + tid;
            int r = e >> 2;
            int c = (e & 3) << 3;
            uint32_t dst = bs_base + (uint32_t)(r * MSTR + c) * 2;
            const __nv_bfloat16* src = B + (size_t)(n0 + r) * K256 + c;
            CP_ASYNC16(dst, src);
        }
        CP_COMMIT();
        CP_WAIT0();
        __syncthreads();

        for (int ks8 = 0; ks8 < 8; ks8++) {
            int cur = ks8 & 1;
            if (ks8 < 7) {
                uint32_t dbuf = bs_base + (uint32_t)((cur ^ 1) * VB_BUF) * 2;
                #pragma unroll
                for (int i = 0; i < 2; i++) {
                    int e = i * 256 + tid;
                    int r = e >> 2;
                    int c = (e & 3) << 3;
                    uint32_t dst = dbuf + (uint32_t)(r * MSTR + c) * 2;
                    const __nv_bfloat16* src = B + (size_t)(n0 + r) * K256 + (ks8 + 1) * 32 + c;
                    CP_ASYNC16(dst, src);
                }
                CP_COMMIT();
            }
            uint32_t cbuf = bs_base + (uint32_t)(cur * VB_BUF) * 2;
            #pragma unroll
            for (int sub = 0; sub < 2; sub++) {
                int kk = ks8 * 32 + sub * 16;
                uint32_t af[4][4];
                #pragma unroll
                for (int mt = 0; mt < 4; mt++) {
                    uint32_t addr = as_base + a_lm_off + (uint32_t)(mt * 16 * ASTRIDE + kk) * 2;
                    asm volatile("ldmatrix.sync.aligned.m8n8.x4.shared.b16 {%0,%1,%2,%3}, [%4];"
                        : "=r"(af[mt][0]), "=r"(af[mt][1]), "=r"(af[mt][2]), "=r"(af[mt][3])
                        : "r"(addr));
                }
                uint32_t bf[4][2];
                #pragma unroll
                for (int nt = 0; nt < 4; nt++) {
                    uint32_t addr = cbuf + b_lm_off + (uint32_t)(nt * 8 * MSTR + sub * 16) * 2;
                    asm volatile("ldmatrix.sync.aligned.m8n8.x2.shared.b16 {%0,%1}, [%2];"
                        : "=r"(bf[nt][0]), "=r"(bf[nt][1]) : "r"(addr));
                }
                #pragma unroll
                for (int mt = 0; mt < 4; mt++)
                    #pragma unroll
                    for (int nt = 0; nt < 4; nt++) {
                        asm volatile(
                            "mma.sync.aligned.m16n8k16.row.col.f32.bf16.bf16.f32 "
                            "{%0,%1,%2,%3}, {%4,%5,%6,%7}, {%8,%9}, {%0,%1,%2,%3};"
                            : "+f"(acc[mt][nt][0]), "+f"(acc[mt][nt][1]),
                              "+f"(acc[mt][nt][2]), "+f"(acc[mt][nt][3])
                            : "r"(af[mt][0]), "r"(af[mt][1]), "r"(af[mt][2]), "r"(af[mt][3]),
                              "r"(bf[nt][0]), "r"(bf[nt][1]));
                    }
            }
            if (ks8 < 7) { CP_WAIT0(); }
            __syncthreads();
        }

        const int head = nh * 4 + warp_n;
        __nv_bfloat16* vh = VT + (size_t)head * HWSZ * HD;
        #pragma unroll
        for (int mt = 0; mt < 4; mt++) {
            #pragma unroll
            for (int nt = 0; nt < 4; nt++) {
                int ch = nt * 8 + col_in;
                int n = n0 + warp_n * 32 + ch;
                float b0 = bias[n], b1 = bias[n + 1];
                #pragma unroll
                for (int half = 0; half < 2; half++) {
                    int m = m0 + warp_m * 64 + mt * 16 + row_in + half * 8;
                    float ox = acc[mt][nt][half * 2 + 0] + b0;
                    float oy = acc[mt][nt][half * 2 + 1] + b1;
                    uint32_t pr;
                    asm("cvt.rn.satfinite.bf16x2.f32 %0, %1, %2;" : "=r"(pr) : "f"(oy), "f"(ox));
                    *reinterpret_cast<uint32_t*>(vh + (size_t)m * HD + ch) = pr;
                }
            }
        }
        __syncthreads();
    }
}

// ---------------------------------------------------------------------------
// Weight prep
// ---------------------------------------------------------------------------
__global__ void prep_all(const float* __restrict__ Wv,  __nv_bfloat16* __restrict__ dWv,
                         const float* __restrict__ Wo,  __nv_bfloat16* __restrict__ dWo,
                         const float* __restrict__ Wp2, __nv_bfloat16* __restrict__ dWp2,
                         const float* __restrict__ Wp3, __nv_bfloat16* __restrict__ dWp3,
                         const float* __restrict__ W1,  __nv_bfloat16* __restrict__ dW1,
                         const float* __restrict__ W2,  __nv_bfloat16* __restrict__ dW2) {
    int i = blockIdx.x * 256 + threadIdx.x;
    const int S = DIM * DIM;
    const int L = DFF * DIM;
    if (i < S)                    dWv[i] = __float2bfloat16(Wv[i]);
    else if (i < 2 * S)           dWo[i - S] = __float2bfloat16(Wo[i - S]);
    else if (i < 3 * S)           dWp2[i - 2 * S] = __float2bfloat16(Wp2[i - 2 * S]);
    else if (i < 4 * S)           dWp3[i - 3 * S] = __float2bfloat16(Wp3[i - 3 * S]);
    else if (i < 4 * S + L)       dW1[i - 4 * S] = __float2bfloat16(W1[i - 4 * S]);
    else if (i < 4 * S + 2 * L)   dW2[i - 4 * S - L] = __float2bfloat16(W2[i - 4 * S - L]);
}

__global__ void pack_wab(const float* __restrict__ Wa, const float* __restrict__ Wb,
                         const float* __restrict__ ba, const float* __restrict__ bb,
                         __nv_bfloat16* __restrict__ Whi, __nv_bfloat16* __restrict__ Wlo,
                         float* __restrict__ bab) {
    int row = blockIdx.x;
    int col = threadIdx.x;
    float w = 0.f;
    if (row < 200)      w = Wa[row * DIM + col];
    else if (row < 240) w = Wb[(row - 200) * DIM + col];
    __nv_bfloat16 hi = __float2bfloat16(w);
    Whi[row * DIM + col] = hi;
    Wlo[row * DIM + col] = __float2bfloat16(w - __bfloat162float(hi));
    if (col == 0) {
        float b = 0.f;
        if (row < 200)      b = ba[row];
        else if (row < 240) b = bb[row - 200];
        bab[row] = b;
    }
}

// ---------------------------------------------------------------------------
// fp32 SGEMM (tiny K=8 first pos-MLP layer)
// ---------------------------------------------------------------------------
#define BM 64
#define BN 64
#define BKT 16

__global__ void sgemm_k8_relu(const float* __restrict__ A, const float* __restrict__ B,
                              const float* __restrict__ bias, float* __restrict__ C,
                              int M, int N, int K) {
    __shared__ float As[BKT][BM];
    __shared__ float Bs[BKT][BN];
    const int tid  = threadIdx.x;
    const int brow = blockIdx.y * BM;
    const int bcol = blockIdx.x * BN;
    const int tx = tid & 15;
    const int ty = tid >> 4;
    const int lr = tid >> 2;
    const int lk = (tid & 3) << 2;

    float acc[4][4] = {};
    for (int k0 = 0; k0 < K; k0 += BKT) {
        #pragma unroll
        for (int i = 0; i < 4; i++) {
            int k = k0 + lk + i;
            As[lk + i][lr] = (k < K) ? A[(size_t)(brow + lr) * K + k] : 0.f;
            Bs[lk + i][lr] = (k < K) ? B[(size_t)(bcol + lr) * K + k] : 0.f;
        }
        __syncthreads();
        #pragma unroll
        for (int kk = 0; kk < BKT; kk++) {
            float4 a4 = *reinterpret_cast<const float4*>(&As[kk][ty << 2]);
            float4 b4 = *reinterpret_cast<const float4*>(&Bs[kk][tx << 2]);
            float ar[4] = {a4.x, a4.y, a4.z, a4.w};
            float br[4] = {b4.x, b4.y, b4.z, b4.w};
            #pragma unroll
            for (int i = 0; i < 4; i++)
                #pragma unroll
                for (int j = 0; j < 4; j++)
                    acc[i][j] = fmaf(ar[i], br[j], acc[i][j]);
        }
        __syncthreads();
    }
    #pragma unroll
    for (int i = 0; i < 4; i++) {
        int r = brow + (ty << 2) + i;
        #pragma unroll
        for (int j = 0; j < 4; j++) {
            int c = bcol + (tx << 2) + j;
            C[(size_t)r * N + c] = fmaxf(acc[i][j] + bias[c], 0.f);
        }
    }
}

// ---------------------------------------------------------------------------
// Deformable bilinear sampling, fused softmax; v head-major [h][HW][32] bf16.
// ---------------------------------------------------------------------------
__global__ void sample_kernel(const float* __restrict__ rw,
                              const float* __restrict__ ao,
                              const __nv_bfloat16* __restrict__ v,
                              float* __restrict__ out) {
    int n    = blockIdx.x;
    int h    = threadIdx.x >> 5;
    int lane = threadIdx.x & 31;

    const float* aon = ao + (size_t)n * DIM;
    float logit = (lane < PP) ? aon[h * PP + lane] : -1e30f;
    float mx = logit;
    #pragma unroll
    for (int o = 16; o; o >>= 1) mx = fmaxf(mx, __shfl_xor_sync(0xffffffffu, mx, o));
    float e = (lane < PP) ? expf(logit - mx) : 0.f;
    float s = e;
    #pragma unroll
    for (int o = 16; o; o >>= 1) s += __shfl_xor_sync(0xffffffffu, s, o);
    float myattn = e / s;

    const float* rwn = rw + (size_t)n * 8;
    float rw0 = rwn[0], rw1 = rwn[1], rw3 = rwn[3], rw4 = rwn[4], rw6 = rwn[6];
    const float* offn = aon + 200 + h * 5;
    float o0 = offn[0], o1 = offn[1], o2 = offn[2], o3 = offn[3], o4 = offn[4];

    float cx = rw0 + o0 * 0.125f * rw3;
    float cy = rw1 + o1 * 0.125f * rw4;
    float sx = fmaxf(rw3 + o2 * 0.125f * rw3, 0.f);
    float sy = fmaxf(rw4 + o3 * 0.125f * rw4, 0.f);
    float ang = (rw6 + o4 * (1.0f / 16.0f)) * 6.2831853071795864769f;
    float sth, cth;
    sincosf(ang, &sth, &cth);

    const __nv_bfloat16* vh = v + (size_t)h * HWSZ * HD + lane;

    float acc = 0.f;
    #pragma unroll
    for (int p = 0; p < PP; p++) {
        int a = p / 5, b = p % 5;
        float gx = sx * (float)(b - 2) * 0.2f;
        float gy = sy * (float)(a - 2) * 0.2f;
        float lx = cx + gx * cth - gy * sth;
        float ly = cy + gx * sth + gy * cth;
        float x = lx * (float)WW - 0.5f;
        float y = ly * (float)HH - 0.5f;
        float x0f = floorf(x), y0f = floorf(y);
        float fx = x - x0f, fy = y - y0f;
        int x0 = (int)x0f, y0 = (int)y0f;
        float ap = __shfl_sync(0xffffffffu, myattn, p);
        #pragma unroll
        for (int c = 0; c < 4; c++) {
            int dx = c & 1, dy = c >> 1;
            int xi = x0 + dx, yi = y0 + dy;
            float wx = dx ? fx : (1.f - fx);
            float wy = dy ? fy : (1.f - fy);
            bool valid = (xi >= 0) && (xi <= WW - 1) && (yi >= 0) && (yi <= HH - 1);
            if (valid) {
                float g = __bfloat162float(vh[(size_t)(yi * WW + xi) * HD]);
                acc = fmaf(ap * wx * wy, g, acc);
            }
        }
    }
    out[(size_t)n * DIM + h * HD + lane] = acc;
}

// ---------------------------------------------------------------------------
// LayerNorm (residual add + LN)
// ---------------------------------------------------------------------------
__global__ void ln_kernel(const float* __restrict__ A, const float* __restrict__ Bb,
                          const float* __restrict__ gamma, const float* __restrict__ beta,
                          float* __restrict__ O) {
    int n = blockIdx.x;
    int c = threadIdx.x;
    float x = A[(size_t)n * DIM + c] + Bb[(size_t)n * DIM + c];
    float s = x, sq = x * x;
    #pragma unroll
    for (int o = 16; o; o >>= 1) {
        s  += __shfl_xor_sync(0xffffffffu, s, o);
        sq += __shfl_xor_sync(0xffffffffu, sq, o);
    }
    __shared__ float sh_s[8], sh_q[8];
    if ((c & 31) == 0) { sh_s[c >> 5] = s; sh_q[c >> 5] = sq; }
    __syncthreads();
    float ts = 0.f, tq = 0.f;
    #pragma unroll
    for (int i = 0; i < 8; i++) { ts += sh_s[i]; tq += sh_q[i]; }
    float mean = ts * (1.0f / (float)DIM);
    float var  = tq * (1.0f / (float)DIM) - mean * mean;
    var = fmaxf(var, 0.f);
    float inv = rsqrtf(var + 1e-5f);
    O[(size_t)n * DIM + c] = (x - mean) * inv * gamma[c] + beta[c];
}

// ---------------------------------------------------------------------------
// Host orchestration — fork vproj onto a side stream, overlap with pos-MLP chain
// ---------------------------------------------------------------------------
extern "C" void kernel_launch(void* const* d_in, const int* in_sizes, int n_in,
                              void* d_out, int out_size) {
    const float* query = (const float*)d_in[0];
    const float* memory = (const float*)d_in[1];
    const float* ref_w  = (const float*)d_in[2];
    const float* Wp1 = (const float*)d_in[5];
    const float* bp1 = (const float*)d_in[6];
    const float* Wp2 = (const float*)d_in[7];
    const float* bp2 = (const float*)d_in[8];
    const float* Wp3 = (const float*)d_in[9];
    const float* bp3 = (const float*)d_in[10];
    const float* Wv  = (const float*)d_in[11];
    const float* bv  = (const float*)d_in[12];
    const float* Wa  = (const float*)d_in[13];
    const float* ba  = (const float*)d_in[14];
    const float* Wb  = (const float*)d_in[15];
    const float* bb  = (const float*)d_in[16];
    const float* Wo  = (const float*)d_in[17];
    const float* bo  = (const float*)d_in[18];
    const float* W1  = (const float*)d_in[19];
    const float* b1  = (const float*)d_in[20];
    const float* W2  = (const float*)d_in[21];
    const float* b2  = (const float*)d_in[22];
    const float* g2  = (const float*)d_in[23];
    const float* be2 = (const float*)d_in[24];
    const float* g3  = (const float*)d_in[25];
    const float* be3 = (const float*)d_in[26];
    float* out = (float*)d_out;

    __nv_bfloat16 *v_bf, *Wv_bf, *Wo_bf, *W1_bf, *W2_bf, *Wp2_bf, *Wp3_bf, *Wab_hi, *Wab_lo;
    float *q, *buf1, *buf2, *smp, *xq, *bab;
    cudaGetSymbolAddress((void**)&v_bf,   g_v_bf);
    cudaGetSymbolAddress((void**)&q,      g_q);
    cudaGetSymbolAddress((void**)&buf1,   g_buf1);
    cudaGetSymbolAddress((void**)&buf2,   g_buf2);
    cudaGetSymbolAddress((void**)&smp,    g_smp);
    cudaGetSymbolAddress((void**)&xq,     g_xq);
    cudaGetSymbolAddress((void**)&Wv_bf,  g_Wv_bf);
    cudaGetSymbolAddress((void**)&Wo_bf,  g_Wo_bf);
    cudaGetSymbolAddress((void**)&W1_bf,  g_W1_bf);
    cudaGetSymbolAddress((void**)&W2_bf,  g_W2_bf);
    cudaGetSymbolAddress((void**)&Wp2_bf, g_Wp2_bf);
    cudaGetSymbolAddress((void**)&Wp3_bf, g_Wp3_bf);
    cudaGetSymbolAddress((void**)&Wab_hi, g_Wab_hi);
    cudaGetSymbolAddress((void**)&Wab_lo, g_Wab_lo);
    cudaGetSymbolAddress((void**)&bab,    g_bab);

    cudaFuncSetAttribute(mma_k256_vproj, cudaFuncAttributeMaxDynamicSharedMemorySize, KSMEM_TOTAL);

    // Side stream + fork/join events (created once; host-side only, re-used
    // deterministically — capture embeds only the kernel nodes + edges)
    static cudaStream_t s1 = nullptr;
    static cudaEvent_t ev_fork = nullptr, ev_join = nullptr;
    if (s1 == nullptr) {
        cudaStreamCreateWithFlags(&s1, cudaStreamNonBlocking);
        cudaEventCreateWithFlags(&ev_fork, cudaEventDisableTiming);
        cudaEventCreateWithFlags(&ev_join, cudaEventDisableTiming);
    }

    // 0) Weight prep (default stream)
    const int PREP_N = 4 * DIM * DIM + 2 * DFF * DIM;
    prep_all<<<(PREP_N + 255) / 256, 256>>>(Wv, Wv_bf, Wo, Wo_bf, Wp2, Wp2_bf,
                                            Wp3, Wp3_bf, W1, W1_bf, W2, W2_bf);

    // Fork: vproj branch depends only on prep_all (Wv_bf)
    cudaEventRecord(ev_fork, 0);
    cudaStreamWaitEvent(s1, ev_fork, 0);
    mma_k256_vproj<<<HWSZ / 128, 256, KSMEM_TOTAL, s1>>>(memory, Wv_bf, bv, v_bf);
    cudaEventRecord(ev_join, s1);

    // Main branch: pos-MLP + Wab chain (overlaps with vproj)
    pack_wab<<<DIM, DIM>>>(Wa, Wb, ba, bb, Wab_hi, Wab_lo, bab);
    sgemm_k8_relu<<<dim3(DIM / BN, NQ / BM), 256>>>(ref_w, Wp1, bp1, buf1, NQ, DIM, 8);
    mma_gemm64<1><<<dim3(2, NQ / 64), 256>>>(buf1, Wp2_bf, bp2, nullptr, buf2, DIM, DIM);
    mma_gemm64<2><<<dim3(2, NQ / 64), 256>>>(buf2, Wp3_bf, bp3, query, q, DIM, DIM);
    mma_gemm_x3<<<dim3(2, NQ / MBM), 256>>>(q, Wab_hi, Wab_lo, bab, buf1, DIM, DIM);

    // Join: sampling needs both v_bf and the logits/offsets
    cudaStreamWaitEvent(0, ev_join, 0);
    sample_kernel<<<NQ, 256>>>(ref_w, buf1, v_bf, smp);

    // Output projection + residual LN
    mma_gemm64<0><<<dim3(2, NQ / 64), 256>>>(smp, Wo_bf, bo, nullptr, buf2, DIM, DIM);
    ln_kernel<<<NQ, 256>>>(query, buf2, g2, be2, xq);

    // FFN + final LN
    mma_gemm<1><<<dim3(DFF / MBN, NQ / MBM), 256>>>(xq, W1_bf, b1, nullptr, buf1, DIM, DFF);
    mma_gemm64<0><<<dim3(2, NQ / 64), 256>>>(buf1, W2_bf, b2, nullptr, buf2, DFF, DIM);
    ln_kernel<<<NQ, 256>>>(xq, buf2, g3, be3, out);
}